// round 2
// baseline (speedup 1.0000x reference)
#include <cuda_runtime.h>
#include <math.h>

#define B_  16
#define S_  1024
#define V_  512
#define E_  8
#define FF_ 2048
#define BV  (B_*V_)   // 8192 tokens (b,v)
#define BS  (B_*S_)   // 16384 rows (b,s)

// -------- scratch (device globals; no allocation allowed) --------
__device__ float g_xt[(size_t)BV * S_];   // x transposed: [B,V,S]
__device__ float g_t [(size_t)BV * S_];   // MoE accumulator [B,V,S]
__device__ float g_x1[(size_t)BS * V_];   // after MoE + residual [B,S,V]
__device__ float g_h [(size_t)BS * FF_];  // fc1 activations [B,S,FF]
__device__ int   g_tok[E_ * BV];          // per-expert gathered token ids
__device__ float g_w  [E_ * BV];          // per-expert gate weights
__device__ int   g_cnt[E_];               // per-expert counts

// -------- zero MoE accumulator + counters (vectorized) --------
__global__ void zero_kernel() {
    size_t i = (size_t)blockIdx.x * blockDim.x + threadIdx.x;
    size_t stride = (size_t)gridDim.x * blockDim.x;
    float4* p = (float4*)g_t;
    size_t n4 = (size_t)BV * S_ / 4;
    float4 z = make_float4(0.f, 0.f, 0.f, 0.f);
    for (size_t j = i; j < n4; j += stride) p[j] = z;
    if (i < E_) g_cnt[i] = 0;
}

// -------- transpose x[B,S,V] -> g_xt[B,V,S] --------
__global__ void transpose_kernel(const float* __restrict__ x) {
    __shared__ float tile[32][33];
    int b = blockIdx.z;
    int s0 = blockIdx.x * 32, v0 = blockIdx.y * 32;
    int tx = threadIdx.x, ty = threadIdx.y;   // (32, 8)
    const float* xp = x + (size_t)b * S_ * V_;
    #pragma unroll
    for (int r = 0; r < 32; r += 8)
        tile[ty + r][tx] = xp[(size_t)(s0 + ty + r) * V_ + v0 + tx];
    __syncthreads();
    float* xtp = g_xt + (size_t)b * V_ * S_;
    #pragma unroll
    for (int r = 0; r < 32; r += 8)
        xtp[(size_t)(v0 + ty + r) * S_ + s0 + tx] = tile[tx][ty + r];
}

// -------- gating: logits, softmax -> probs, top-2 -> expert lists --------
__global__ void __launch_bounds__(256) gating_kernel(const float* __restrict__ gate_W,
                                                     float* __restrict__ out_probs) {
    __shared__ float sgw[E_ * S_];        // 32 KB
    int tid = threadIdx.x;
    for (int i = tid; i < E_ * S_; i += 256) sgw[i] = gate_W[i];
    __syncthreads();

    int warp = tid >> 5, lane = tid & 31;
    int tok = blockIdx.x * 8 + warp;      // one warp per token
    const float* row = g_xt + (size_t)tok * S_;

    float acc[E_] = {};
    for (int s = lane; s < S_; s += 32) {
        float xv = row[s];
        #pragma unroll
        for (int e = 0; e < E_; e++) acc[e] = fmaf(xv, sgw[e * S_ + s], acc[e]);
    }
    #pragma unroll
    for (int e = 0; e < E_; e++)
        #pragma unroll
        for (int o = 16; o > 0; o >>= 1)
            acc[e] += __shfl_down_sync(0xffffffffu, acc[e], o);

    if (lane == 0) {
        float m = acc[0];
        #pragma unroll
        for (int e = 1; e < E_; e++) m = fmaxf(m, acc[e]);
        float p[E_], sum = 0.f;
        #pragma unroll
        for (int e = 0; e < E_; e++) { p[e] = expf(acc[e] - m); sum += p[e]; }
        float inv = 1.f / sum;
        #pragma unroll
        for (int e = 0; e < E_; e++) { p[e] *= inv; out_probs[(size_t)tok * E_ + e] = p[e]; }
        // top-2, first-occurrence tie-break (matches jax top_k)
        int i0 = 0;
        #pragma unroll
        for (int e = 1; e < E_; e++) if (p[e] > p[i0]) i0 = e;
        int i1 = -1;
        #pragma unroll
        for (int e = 0; e < E_; e++) {
            if (e == i0) continue;
            if (i1 < 0 || p[e] > p[i1]) i1 = e;
        }
        int pos0 = atomicAdd(&g_cnt[i0], 1);
        g_tok[i0 * BV + pos0] = tok; g_w[i0 * BV + pos0] = p[i0];
        int pos1 = atomicAdd(&g_cnt[i1], 1);
        g_tok[i1 * BV + pos1] = tok; g_w[i1 * BV + pos1] = p[i1];
    }
}

// -------- MoE: per-expert gathered GEMM, scatter-add w*(out + b) --------
// C[i,o] = sum_s xt[tok[i],s] * exp_W[e,o,s]; t[tok[i],o] += w[i]*(C+b[e,o])
__global__ void __launch_bounds__(256) moe_gemm_kernel(const float* __restrict__ exp_W,
                                                       const float* __restrict__ exp_b) {
    int e = blockIdx.z;
    int cnt = g_cnt[e];
    int m0 = blockIdx.y * 128;
    if (m0 >= cnt) return;
    int n0 = blockIdx.x * 128;

    __shared__ float As[16][128];
    __shared__ float Bs[16][128];
    __shared__ int   stok[128];
    __shared__ float sw[128];

    int tid = threadIdx.x;
    if (tid < 128) {
        int gr = m0 + tid;
        if (gr < cnt) { stok[tid] = g_tok[e * BV + gr]; sw[tid] = g_w[e * BV + gr]; }
        else          { stok[tid] = 0;                  sw[tid] = 0.f; }
    }
    __syncthreads();

    int tx = tid & 15, ty = tid >> 4;
    float acc[8][8] = {};
    const float* Wp = exp_W + (size_t)e * S_ * S_;

    for (int k0 = 0; k0 < S_; k0 += 16) {
        #pragma unroll
        for (int it = 0; it < 2; it++) {
            int idx = tid + it * 256;
            int row = idx >> 2, k4 = (idx & 3) * 4;
            float4 v = *(const float4*)(g_xt + (size_t)stok[row] * S_ + k0 + k4);
            As[k4 + 0][row] = v.x; As[k4 + 1][row] = v.y;
            As[k4 + 2][row] = v.z; As[k4 + 3][row] = v.w;
            float4 u = *(const float4*)(Wp + (size_t)(n0 + row) * S_ + k0 + k4);
            Bs[k4 + 0][row] = u.x; Bs[k4 + 1][row] = u.y;
            Bs[k4 + 2][row] = u.z; Bs[k4 + 3][row] = u.w;
        }
        __syncthreads();
        #pragma unroll
        for (int kk = 0; kk < 16; kk++) {
            float a[8], b[8];
            #pragma unroll
            for (int i = 0; i < 8; i++) a[i] = As[kk][ty * 8 + i];
            #pragma unroll
            for (int j = 0; j < 8; j++) b[j] = Bs[kk][tx * 8 + j];
            #pragma unroll
            for (int i = 0; i < 8; i++)
                #pragma unroll
                for (int j = 0; j < 8; j++)
                    acc[i][j] = fmaf(a[i], b[j], acc[i][j]);
        }
        __syncthreads();
    }

    #pragma unroll
    for (int i = 0; i < 8; i++) {
        int lr = ty * 8 + i;
        if (m0 + lr >= cnt) continue;
        float wr = sw[lr];
        float* trow = g_t + (size_t)stok[lr] * S_;
        #pragma unroll
        for (int j = 0; j < 8; j++) {
            int col = n0 + tx * 8 + j;
            atomicAdd(&trow[col], wr * (acc[i][j] + exp_b[e * S_ + col]));
        }
    }
}

// -------- relu(MoE) transposed back + residual -> g_x1[B,S,V] --------
__global__ void addres_kernel(const float* __restrict__ x) {
    __shared__ float tile[32][33];
    int b = blockIdx.z;
    int v0 = blockIdx.x * 32, s0 = blockIdx.y * 32;
    int tx = threadIdx.x, ty = threadIdx.y;   // (32, 8)
    const float* tp = g_t + (size_t)b * V_ * S_;
    #pragma unroll
    for (int r = 0; r < 32; r += 8)
        tile[ty + r][tx] = tp[(size_t)(v0 + ty + r) * S_ + s0 + tx];  // tile[v][s]
    __syncthreads();
    const float* xp = x + (size_t)b * S_ * V_;
    float* op = g_x1 + (size_t)b * S_ * V_;
    #pragma unroll
    for (int r = 0; r < 32; r += 8) {
        float tv = tile[tx][ty + r];            // t[v0+tx][s0+ty+r]
        size_t o = (size_t)(s0 + ty + r) * V_ + v0 + tx;
        op[o] = fmaxf(tv, 0.f) + xp[o];
    }
}

// -------- generic TN SGEMM body: C = A[M,K]*Bm[N,K]^T + bias (+res) --------
template<int KDIM, int N, bool RELU, bool RES>
__device__ __forceinline__ void gemm_body(const float* __restrict__ A,
                                          const float* __restrict__ Bm,
                                          const float* __restrict__ bias,
                                          const float* __restrict__ res,
                                          float* __restrict__ C) {
    __shared__ float As[16][128];
    __shared__ float Bs[16][128];
    int tid = threadIdx.x;
    int m0 = blockIdx.y * 128, n0 = blockIdx.x * 128;
    int tx = tid & 15, ty = tid >> 4;
    float acc[8][8] = {};

    for (int k0 = 0; k0 < KDIM; k0 += 16) {
        #pragma unroll
        for (int it = 0; it < 2; it++) {
            int idx = tid + it * 256;
            int row = idx >> 2, k4 = (idx & 3) * 4;
            float4 v = *(const float4*)(A + (size_t)(m0 + row) * KDIM + k0 + k4);
            As[k4 + 0][row] = v.x; As[k4 + 1][row] = v.y;
            As[k4 + 2][row] = v.z; As[k4 + 3][row] = v.w;
            float4 u = *(const float4*)(Bm + (size_t)(n0 + row) * KDIM + k0 + k4);
            Bs[k4 + 0][row] = u.x; Bs[k4 + 1][row] = u.y;
            Bs[k4 + 2][row] = u.z; Bs[k4 + 3][row] = u.w;
        }
        __syncthreads();
        #pragma unroll
        for (int kk = 0; kk < 16; kk++) {
            float a[8], b[8];
            #pragma unroll
            for (int i = 0; i < 8; i++) a[i] = As[kk][ty * 8 + i];
            #pragma unroll
            for (int j = 0; j < 8; j++) b[j] = Bs[kk][tx * 8 + j];
            #pragma unroll
            for (int i = 0; i < 8; i++)
                #pragma unroll
                for (int j = 0; j < 8; j++)
                    acc[i][j] = fmaf(a[i], b[j], acc[i][j]);
        }
        __syncthreads();
    }

    #pragma unroll
    for (int i = 0; i < 8; i++) {
        int r = m0 + ty * 8 + i;
        #pragma unroll
        for (int j = 0; j < 8; j++) {
            int n = n0 + tx * 8 + j;
            float v = acc[i][j] + bias[n];
            if (RELU) v = fmaxf(v, 0.f);
            if (RES)  v += res[(size_t)r * N + n];
            C[(size_t)r * N + n] = v;
        }
    }
}

__global__ void __launch_bounds__(256) fc1_kernel(const float* __restrict__ W,
                                                  const float* __restrict__ b) {
    gemm_body<V_, FF_, true, false>(g_x1, W, b, nullptr, g_h);
}
__global__ void __launch_bounds__(256) fc2_kernel(const float* __restrict__ W,
                                                  const float* __restrict__ b,
                                                  float* __restrict__ out) {
    gemm_body<FF_, V_, false, true>(g_h, W, b, g_x1, out);
}

extern "C" void kernel_launch(void* const* d_in, const int* in_sizes, int n_in,
                              void* d_out, int out_size) {
    const float* x      = (const float*)d_in[0];
    const float* gate_W = (const float*)d_in[1];
    const float* exp_W  = (const float*)d_in[2];
    const float* exp_b  = (const float*)d_in[3];
    const float* fc1_W  = (const float*)d_in[4];
    const float* fc1_b  = (const float*)d_in[5];
    const float* fc2_W  = (const float*)d_in[6];
    const float* fc2_b  = (const float*)d_in[7];
    float* out       = (float*)d_out;
    float* out_probs = out + (size_t)B_ * S_ * V_;   // tuple: (x, probs)

    dim3 tb(32, 8);
    zero_kernel<<<2048, 256>>>();
    transpose_kernel<<<dim3(S_ / 32, V_ / 32, B_), tb>>>(x);
    gating_kernel<<<BV / 8, 256>>>(gate_W, out_probs);
    moe_gemm_kernel<<<dim3(S_ / 128, BV / 128, E_), 256>>>(exp_W, exp_b);
    addres_kernel<<<dim3(V_ / 32, S_ / 32, B_), tb>>>(x);
    fc1_kernel<<<dim3(FF_ / 128, BS / 128), 256>>>(fc1_W, fc1_b);
    fc2_kernel<<<dim3(V_ / 128, BS / 128), 256>>>(fc2_W, fc2_b, out);
}

// round 8
// speedup vs baseline: 1.9684x; 1.9684x over previous
#include <cuda_runtime.h>
#include <cuda_bf16.h>
#include <cstdint>
#include <math.h>

#define B_  16
#define S_  1024
#define V_  512
#define E_  8
#define FF_ 2048
#define BV  (B_*V_)   // 8192 tokens (b,v)
#define BS  (B_*S_)   // 16384 rows (b,s)

// ================= device scratch (no allocation allowed) =================
// A-side bf16 layout per row (K' = 3K): [hi | lo | hi]
// B-side bf16 layout per row (K' = 3K): [hi | hi | lo]
// => sum over K' = Ah*Bh + Al*Bh + Ah*Bl   (drops only Al*Bl ~ 2^-18)
__device__ float          g_xt   [(size_t)BV * S_];         // x^T fp32 (gating)
__device__ __nv_bfloat16  g_xt_bf[(size_t)BV * 3 * S_];     // MoE A
__device__ float          g_part [2][(size_t)BV * S_];      // per-slot MoE outputs
__device__ float          g_x1   [(size_t)BS * V_];         // MoE+res fp32 (fc2 residual)
__device__ __nv_bfloat16  g_x1_bf[(size_t)BS * 3 * V_];     // fc1 A
__device__ __nv_bfloat16  g_h_bf [(size_t)BS * 3 * FF_];    // fc2 A
__device__ __nv_bfloat16  g_eW_bf[(size_t)E_ * S_ * 3 * S_];   // MoE B
__device__ __nv_bfloat16  g_f1W_bf[(size_t)FF_ * 3 * V_];      // fc1 B
__device__ __nv_bfloat16  g_f2W_bf[(size_t)V_ * 3 * FF_];      // fc2 B
__device__ int   g_tok [E_ * BV];
__device__ float g_w   [E_ * BV];
__device__ int   g_slot[E_ * BV];
__device__ int   g_cnt [E_];

__device__ __forceinline__ uint32_t smem_u32(const void* p) {
    uint32_t a;
    asm("{ .reg .u64 t; cvta.to.shared.u64 t, %1; cvt.u32.u64 %0, t; }" : "=r"(a) : "l"(p));
    return a;
}
#define LDSM4(r, a) \
    asm volatile("ldmatrix.sync.aligned.m8n8.x4.shared.b16 {%0,%1,%2,%3}, [%4];" \
                 : "=r"((r)[0]), "=r"((r)[1]), "=r"((r)[2]), "=r"((r)[3]) : "r"(a))
#define MMA16816(d, a, b0v, b1v) \
    asm volatile("mma.sync.aligned.m16n8k16.row.col.f32.bf16.bf16.f32 " \
                 "{%0,%1,%2,%3},{%4,%5,%6,%7},{%8,%9},{%0,%1,%2,%3};" \
                 : "+f"((d)[0]), "+f"((d)[1]), "+f"((d)[2]), "+f"((d)[3]) \
                 : "r"((a)[0]), "r"((a)[1]), "r"((a)[2]), "r"((a)[3]), "r"(b0v), "r"(b1v))

// ================= small kernels =================
__global__ void zero_cnt_kernel() { if (threadIdx.x < E_) g_cnt[threadIdx.x] = 0; }

// transpose x[B,S,V] -> g_xt fp32 + g_xt_bf [hi|lo|hi]
__global__ void transpose_kernel(const float* __restrict__ x) {
    __shared__ float tile[32][33];
    int b = blockIdx.z;
    int s0 = blockIdx.x * 32, v0 = blockIdx.y * 32;
    int tx = threadIdx.x, ty = threadIdx.y;   // (32, 8)
    const float* xp = x + (size_t)b * S_ * V_;
    #pragma unroll
    for (int r = 0; r < 32; r += 8)
        tile[ty + r][tx] = xp[(size_t)(s0 + ty + r) * V_ + v0 + tx];
    __syncthreads();
    #pragma unroll
    for (int r = 0; r < 32; r += 8) {
        float v = tile[tx][ty + r];
        size_t bv = (size_t)b * V_ + v0 + ty + r;
        int s = s0 + tx;
        g_xt[bv * S_ + s] = v;
        __nv_bfloat16 h = __float2bfloat16(v);
        __nv_bfloat16 l = __float2bfloat16(v - __bfloat162float(h));
        __nv_bfloat16* dst = g_xt_bf + bv * 3 * S_;
        dst[s] = h; dst[S_ + s] = l; dst[2 * S_ + s] = h;
    }
}

// weight split (B side): in[rows][K] fp32 -> out[rows][3K] = [hi|hi|lo]
template<int KLOG>
__global__ void split_kernel(const float* __restrict__ in, __nv_bfloat16* __restrict__ out,
                             size_t total) {
    const int K = 1 << KLOG;
    size_t i = (size_t)blockIdx.x * blockDim.x + threadIdx.x;
    size_t stride = (size_t)gridDim.x * blockDim.x;
    for (size_t idx = i; idx < total; idx += stride) {
        size_t r = idx >> KLOG;
        int k = (int)(idx & (K - 1));
        float v = in[idx];
        __nv_bfloat16 h = __float2bfloat16(v);
        __nv_bfloat16 l = __float2bfloat16(v - __bfloat162float(h));
        __nv_bfloat16* dst = out + r * 3 * K;
        dst[k] = h; dst[K + k] = h; dst[2 * K + k] = l;
    }
}

// gating: softmax probs + top-2 expert lists (with slot ids)
__global__ void __launch_bounds__(256) gating_kernel(const float* __restrict__ gate_W,
                                                     float* __restrict__ out_probs) {
    __shared__ float sgw[E_ * S_];
    int tid = threadIdx.x;
    for (int i = tid; i < E_ * S_; i += 256) sgw[i] = gate_W[i];
    __syncthreads();
    int warp = tid >> 5, lane = tid & 31;
    int tok = blockIdx.x * 8 + warp;
    const float* row = g_xt + (size_t)tok * S_;
    float acc[E_] = {};
    for (int s = lane; s < S_; s += 32) {
        float xv = row[s];
        #pragma unroll
        for (int e = 0; e < E_; e++) acc[e] = fmaf(xv, sgw[e * S_ + s], acc[e]);
    }
    #pragma unroll
    for (int e = 0; e < E_; e++)
        #pragma unroll
        for (int o = 16; o > 0; o >>= 1)
            acc[e] += __shfl_down_sync(0xffffffffu, acc[e], o);
    if (lane == 0) {
        float m = acc[0];
        #pragma unroll
        for (int e = 1; e < E_; e++) m = fmaxf(m, acc[e]);
        float p[E_], sum = 0.f;
        #pragma unroll
        for (int e = 0; e < E_; e++) { p[e] = expf(acc[e] - m); sum += p[e]; }
        float inv = 1.f / sum;
        #pragma unroll
        for (int e = 0; e < E_; e++) { p[e] *= inv; out_probs[(size_t)tok * E_ + e] = p[e]; }
        int i0 = 0;
        #pragma unroll
        for (int e = 1; e < E_; e++) if (p[e] > p[i0]) i0 = e;
        int i1 = -1;
        #pragma unroll
        for (int e = 0; e < E_; e++) {
            if (e == i0) continue;
            if (i1 < 0 || p[e] > p[i1]) i1 = e;
        }
        int pos0 = atomicAdd(&g_cnt[i0], 1);
        g_tok[i0 * BV + pos0] = tok; g_w[i0 * BV + pos0] = p[i0]; g_slot[i0 * BV + pos0] = 0;
        int pos1 = atomicAdd(&g_cnt[i1], 1);
        g_tok[i1 * BV + pos1] = tok; g_w[i1 * BV + pos1] = p[i1]; g_slot[i1 * BV + pos1] = 1;
    }
}

// combine slots + relu + transpose back + residual -> g_x1 fp32 + g_x1_bf [hi|lo|hi]
__global__ void addres_kernel(const float* __restrict__ x) {
    __shared__ float tile[32][33];
    int b = blockIdx.z;
    int v0 = blockIdx.x * 32, s0 = blockIdx.y * 32;
    int tx = threadIdx.x, ty = threadIdx.y;
    #pragma unroll
    for (int r = 0; r < 32; r += 8) {
        size_t o = ((size_t)b * V_ + v0 + ty + r) * S_ + s0 + tx;
        tile[ty + r][tx] = g_part[0][o] + g_part[1][o];
    }
    __syncthreads();
    const float* xp = x + (size_t)b * S_ * V_;
    #pragma unroll
    for (int r = 0; r < 32; r += 8) {
        float tv = fmaxf(tile[tx][ty + r], 0.f);
        int s = s0 + ty + r, v = v0 + tx;
        size_t o = (size_t)s * V_ + v;
        float val = tv + xp[o];
        size_t bs = (size_t)b * S_ + s;
        g_x1[bs * V_ + v] = val;
        __nv_bfloat16 h = __float2bfloat16(val);
        __nv_bfloat16 l = __float2bfloat16(val - __bfloat162float(h));
        __nv_bfloat16* dst = g_x1_bf + bs * 3 * V_;
        dst[v] = h; dst[V_ + v] = l; dst[2 * V_ + v] = h;
    }
}

// ================= HMMA bf16 GEMM: 128x128 CTA tile, BK=32, double-buffered =================
// MODE 0: MoE (gathered A rows, scaled scatter to g_part)
// MODE 1: fc1 (bias+relu -> g_h_bf 3-way split)
// MODE 2: fc2 (bias+residual -> out fp32)
#define LDA 40   // padded bf16 stride (conflict-free ldmatrix)

template<int MODE, int K3, int NDIM>
__global__ void __launch_bounds__(256) mma_kernel(const __nv_bfloat16* __restrict__ A,
                                                  const __nv_bfloat16* __restrict__ Bm,
                                                  const float* __restrict__ bias,
                                                  float* __restrict__ out) {
    constexpr int NKT = K3 / 32;
    __shared__ __align__(16) __nv_bfloat16 sA[2][128 * LDA];
    __shared__ __align__(16) __nv_bfloat16 sB[2][128 * LDA];
    __shared__ int   s_tok[128];
    __shared__ float s_w[128];
    __shared__ int   s_slot[128];

    const int tid = threadIdx.x;
    const int e = (MODE == 0) ? blockIdx.z : 0;
    const int m0 = blockIdx.y * 128;
    const int n0 = blockIdx.x * 128;
    int cnt;
    if (MODE == 0) { cnt = g_cnt[e]; if (m0 >= cnt) return; }
    else cnt = 1 << 30;

    const __nv_bfloat16* Bp = (MODE == 0) ? (Bm + (size_t)e * S_ * K3) : Bm;
    const float* biasp = (MODE == 0) ? (bias + e * S_) : bias;

    if (MODE == 0) {
        if (tid < 128) {
            int gr = m0 + tid;
            if (gr < cnt) { s_tok[tid] = g_tok[e * BV + gr]; s_w[tid] = g_w[e * BV + gr];
                            s_slot[tid] = g_slot[e * BV + gr]; }
            else          { s_tok[tid] = 0; s_w[tid] = 0.f; s_slot[tid] = 0; }
        }
        __syncthreads();
    }

    // per-thread gmem chunk map: 2 chunks for A, 2 for B (16B each)
    const __nv_bfloat16* aptr[2];
    const __nv_bfloat16* bptr[2];
    uint32_t sAo[2], sBo[2];
    #pragma unroll
    for (int i = 0; i < 2; i++) {
        int c = tid + i * 256;
        int row = c >> 2, kc = c & 3;
        if (MODE == 0) aptr[i] = A + (size_t)s_tok[row] * K3 + kc * 8;
        else           aptr[i] = A + (size_t)(m0 + row) * K3 + kc * 8;
        bptr[i] = Bp + (size_t)(n0 + row) * K3 + kc * 8;
        sAo[i] = (uint32_t)(row * LDA + kc * 8);
        sBo[i] = sAo[i];
    }

    float acc[2][8][4];
    #pragma unroll
    for (int mi = 0; mi < 2; mi++)
        #pragma unroll
        for (int nf = 0; nf < 8; nf++)
            #pragma unroll
            for (int q = 0; q < 4; q++) acc[mi][nf][q] = 0.f;

    const int lane = tid & 31, wid = tid >> 5;
    const int wm = wid & 3, wn = wid >> 2;   // warp tile: rows wm*32, cols wn*64

    uint4 pa[2], pb[2];
    #pragma unroll
    for (int i = 0; i < 2; i++) {
        pa[i] = *reinterpret_cast<const uint4*>(aptr[i]);
        pb[i] = *reinterpret_cast<const uint4*>(bptr[i]);
    }
    #pragma unroll
    for (int i = 0; i < 2; i++) {
        *reinterpret_cast<uint4*>(&sA[0][sAo[i]]) = pa[i];
        *reinterpret_cast<uint4*>(&sB[0][sBo[i]]) = pb[i];
    }
    __syncthreads();

    const int a_r = wm * 32 + (lane & 15);
    const int b_r = wn * 64 + (lane & 7) + ((lane >> 3) & 1) * 8;
    const int k_half = (lane >> 4) << 3;

    #pragma unroll 1
    for (int kt = 0; kt < NKT; kt++) {
        const int cur = kt & 1;
        if (kt + 1 < NKT) {
            #pragma unroll
            for (int i = 0; i < 2; i++) {
                pa[i] = *reinterpret_cast<const uint4*>(aptr[i] + (kt + 1) * 32);
                pb[i] = *reinterpret_cast<const uint4*>(bptr[i] + (kt + 1) * 32);
            }
        }
        const uint32_t sAb = smem_u32(&sA[cur][0]);
        const uint32_t sBb = smem_u32(&sB[cur][0]);
        #pragma unroll
        for (int k16 = 0; k16 < 32; k16 += 16) {
            uint32_t aF[2][4], bF[4][4];
            #pragma unroll
            for (int mi = 0; mi < 2; mi++) {
                uint32_t ad = sAb + ((a_r + mi * 16) * LDA + k16 + k_half) * 2;
                LDSM4(aF[mi], ad);
            }
            #pragma unroll
            for (int nq = 0; nq < 4; nq++) {
                uint32_t bd = sBb + ((b_r + nq * 16) * LDA + k16 + k_half) * 2;
                LDSM4(bF[nq], bd);
            }
            #pragma unroll
            for (int mi = 0; mi < 2; mi++)
                #pragma unroll
                for (int nq = 0; nq < 4; nq++) {
                    MMA16816(acc[mi][nq * 2 + 0], aF[mi], bF[nq][0], bF[nq][2]);
                    MMA16816(acc[mi][nq * 2 + 1], aF[mi], bF[nq][1], bF[nq][3]);
                }
        }
        if (kt + 1 < NKT) {
            const int nxt = cur ^ 1;
            __syncthreads();   // all warps done reading buf nxt (iter kt-1)
            #pragma unroll
            for (int i = 0; i < 2; i++) {
                *reinterpret_cast<uint4*>(&sA[nxt][sAo[i]]) = pa[i];
                *reinterpret_cast<uint4*>(&sB[nxt][sBo[i]]) = pb[i];
            }
            __syncthreads();
        }
    }

    // ---- epilogue straight from C fragments ----
    const int g = lane >> 2, t = lane & 3;
    #pragma unroll
    for (int mi = 0; mi < 2; mi++) {
        #pragma unroll
        for (int nf = 0; nf < 8; nf++) {
            const int col = n0 + wn * 64 + nf * 8 + 2 * t;
            const float b0 = biasp[col], b1 = biasp[col + 1];
            #pragma unroll
            for (int h = 0; h < 2; h++) {   // h=0: row g, h=1: row g+8
                const int lr = wm * 32 + mi * 16 + g + h * 8;
                float v0 = acc[mi][nf][h * 2 + 0] + b0;
                float v1 = acc[mi][nf][h * 2 + 1] + b1;
                if (MODE == 0) {
                    if (m0 + lr < cnt) {
                        float wgt = s_w[lr];
                        float* dst = g_part[s_slot[lr]] + (size_t)s_tok[lr] * S_ + col;
                        *reinterpret_cast<float2*>(dst) = make_float2(wgt * v0, wgt * v1);
                    }
                } else if (MODE == 1) {
                    v0 = fmaxf(v0, 0.f); v1 = fmaxf(v1, 0.f);
                    size_t row = (size_t)(m0 + lr);
                    __nv_bfloat16 h0 = __float2bfloat16(v0);
                    __nv_bfloat16 h1 = __float2bfloat16(v1);
                    __nv_bfloat16 l0 = __float2bfloat16(v0 - __bfloat162float(h0));
                    __nv_bfloat16 l1 = __float2bfloat16(v1 - __bfloat162float(h1));
                    __nv_bfloat16* base = g_h_bf + row * 3 * FF_ + col;
                    *reinterpret_cast<__nv_bfloat162*>(base) = __nv_bfloat162(h0, h1);
                    *reinterpret_cast<__nv_bfloat162*>(base + FF_) = __nv_bfloat162(l0, l1);
                    *reinterpret_cast<__nv_bfloat162*>(base + 2 * FF_) = __nv_bfloat162(h0, h1);
                } else {
                    size_t row = (size_t)(m0 + lr);
                    const float2 r2 = *reinterpret_cast<const float2*>(
                        g_x1 + row * NDIM + col);
                    *reinterpret_cast<float2*>(out + row * NDIM + col) =
                        make_float2(v0 + r2.x, v1 + r2.y);
                }
            }
        }
    }
}

// ================= launch =================
extern "C" void kernel_launch(void* const* d_in, const int* in_sizes, int n_in,
                              void* d_out, int out_size) {
    const float* x      = (const float*)d_in[0];
    const float* gate_W = (const float*)d_in[1];
    const float* exp_W  = (const float*)d_in[2];
    const float* exp_b  = (const float*)d_in[3];
    const float* fc1_W  = (const float*)d_in[4];
    const float* fc1_b  = (const float*)d_in[5];
    const float* fc2_W  = (const float*)d_in[6];
    const float* fc2_b  = (const float*)d_in[7];
    float* out       = (float*)d_out;
    float* out_probs = out + (size_t)B_ * S_ * V_;   // tuple: (x, probs)

    __nv_bfloat16 *p_xt_bf, *p_eW, *p_f1W, *p_f2W, *p_x1_bf, *p_h_bf;
    cudaGetSymbolAddress((void**)&p_xt_bf, g_xt_bf);
    cudaGetSymbolAddress((void**)&p_eW,  g_eW_bf);
    cudaGetSymbolAddress((void**)&p_f1W, g_f1W_bf);
    cudaGetSymbolAddress((void**)&p_f2W, g_f2W_bf);
    cudaGetSymbolAddress((void**)&p_x1_bf, g_x1_bf);
    cudaGetSymbolAddress((void**)&p_h_bf,  g_h_bf);

    dim3 tb(32, 8);
    zero_cnt_kernel<<<1, 32>>>();
    transpose_kernel<<<dim3(S_ / 32, V_ / 32, B_), tb>>>(x);
    split_kernel<10><<<2048, 256>>>(exp_W, p_eW, (size_t)E_ * S_ * S_);
    split_kernel<9><<<1024, 256>>>(fc1_W, p_f1W, (size_t)FF_ * V_);
    split_kernel<11><<<1024, 256>>>(fc2_W, p_f2W, (size_t)V_ * FF_);
    gating_kernel<<<BV / 8, 256>>>(gate_W, out_probs);
    mma_kernel<0, 3 * S_, S_><<<dim3(S_ / 128, BV / 128, E_), 256>>>(
        p_xt_bf, p_eW, exp_b, nullptr);
    addres_kernel<<<dim3(V_ / 32, S_ / 32, B_), tb>>>(x);
    mma_kernel<1, 3 * V_, FF_><<<dim3(FF_ / 128, BS / 128, 1), 256>>>(
        p_x1_bf, p_f1W, fc1_b, nullptr);
    mma_kernel<2, 3 * FF_, V_><<<dim3(V_ / 128, BS / 128, 1), 256>>>(
        p_h_bf, p_f2W, fc2_b, out);
}

// round 9
// speedup vs baseline: 5.0925x; 2.5872x over previous
#include <cuda_runtime.h>
#include <cuda_fp16.h>
#include <cstdint>
#include <math.h>

#define B_  16
#define S_  1024
#define V_  512
#define E_  8
#define FF_ 2048
#define BV  (B_*V_)   // 8192 tokens (b,v)
#define BS  (B_*S_)   // 16384 rows (b,s)

// ================= device scratch (no allocation allowed) =================
__device__ float  g_xt   [(size_t)BV * S_];      // x^T fp32 (gating)
__device__ __half g_xt_h [(size_t)BV * S_];      // MoE A (fp16)
__device__ float  g_part [2][(size_t)BV * S_];   // per-slot MoE outputs
__device__ float  g_x1   [(size_t)BS * V_];      // MoE+res fp32 (fc2 residual)
__device__ __half g_x1_h [(size_t)BS * V_];      // fc1 A (fp16)
__device__ __half g_h_h  [(size_t)BS * FF_];     // fc2 A (fp16)
__device__ __half g_eW_h [(size_t)E_ * S_ * S_]; // MoE B (fp16)
__device__ __half g_f1W_h[(size_t)FF_ * V_];     // fc1 B
__device__ __half g_f2W_h[(size_t)V_ * FF_];     // fc2 B
__device__ int   g_tok [E_ * BV];
__device__ float g_w   [E_ * BV];
__device__ int   g_slot[E_ * BV];
__device__ int   g_cnt [E_];

__device__ __forceinline__ uint32_t smem_u32(const void* p) {
    uint32_t a;
    asm("{ .reg .u64 t; cvta.to.shared.u64 t, %1; cvt.u32.u64 %0, t; }" : "=r"(a) : "l"(p));
    return a;
}
#define LDSM4(r, a) \
    asm volatile("ldmatrix.sync.aligned.m8n8.x4.shared.b16 {%0,%1,%2,%3}, [%4];" \
                 : "=r"((r)[0]), "=r"((r)[1]), "=r"((r)[2]), "=r"((r)[3]) : "r"(a))
#define MMA16816(d, a, b0v, b1v) \
    asm volatile("mma.sync.aligned.m16n8k16.row.col.f32.f16.f16.f32 " \
                 "{%0,%1,%2,%3},{%4,%5,%6,%7},{%8,%9},{%0,%1,%2,%3};" \
                 : "+f"((d)[0]), "+f"((d)[1]), "+f"((d)[2]), "+f"((d)[3]) \
                 : "r"((a)[0]), "r"((a)[1]), "r"((a)[2]), "r"((a)[3]), "r"(b0v), "r"(b1v))

// ================= small kernels =================
__global__ void zero_cnt_kernel() { if (threadIdx.x < E_) g_cnt[threadIdx.x] = 0; }

// fp32 -> fp16 cast (weights), vectorized 4-wide
__global__ void cast_kernel(const float* __restrict__ in, __half* __restrict__ out,
                            size_t total4) {
    size_t i = (size_t)blockIdx.x * blockDim.x + threadIdx.x;
    size_t stride = (size_t)gridDim.x * blockDim.x;
    for (size_t idx = i; idx < total4; idx += stride) {
        float4 v = reinterpret_cast<const float4*>(in)[idx];
        __half2 h0 = __floats2half2_rn(v.x, v.y);
        __half2 h1 = __floats2half2_rn(v.z, v.w);
        reinterpret_cast<__half2*>(out)[idx * 2 + 0] = h0;
        reinterpret_cast<__half2*>(out)[idx * 2 + 1] = h1;
    }
}

// transpose x[B,S,V] -> g_xt fp32 + g_xt_h fp16
__global__ void transpose_kernel(const float* __restrict__ x) {
    __shared__ float tile[32][33];
    int b = blockIdx.z;
    int s0 = blockIdx.x * 32, v0 = blockIdx.y * 32;
    int tx = threadIdx.x, ty = threadIdx.y;   // (32, 8)
    const float* xp = x + (size_t)b * S_ * V_;
    #pragma unroll
    for (int r = 0; r < 32; r += 8)
        tile[ty + r][tx] = xp[(size_t)(s0 + ty + r) * V_ + v0 + tx];
    __syncthreads();
    #pragma unroll
    for (int r = 0; r < 32; r += 8) {
        float v = tile[tx][ty + r];
        size_t o = ((size_t)b * V_ + v0 + ty + r) * S_ + s0 + tx;
        g_xt[o] = v;
        g_xt_h[o] = __float2half(v);
    }
}

// gating: softmax probs + top-2 expert lists (with slot ids)
__global__ void __launch_bounds__(256) gating_kernel(const float* __restrict__ gate_W,
                                                     float* __restrict__ out_probs) {
    __shared__ float sgw[E_ * S_];
    int tid = threadIdx.x;
    for (int i = tid; i < E_ * S_; i += 256) sgw[i] = gate_W[i];
    __syncthreads();
    int warp = tid >> 5, lane = tid & 31;
    int tok = blockIdx.x * 8 + warp;
    const float* row = g_xt + (size_t)tok * S_;
    float acc[E_] = {};
    for (int s = lane; s < S_; s += 32) {
        float xv = row[s];
        #pragma unroll
        for (int e = 0; e < E_; e++) acc[e] = fmaf(xv, sgw[e * S_ + s], acc[e]);
    }
    #pragma unroll
    for (int e = 0; e < E_; e++)
        #pragma unroll
        for (int o = 16; o > 0; o >>= 1)
            acc[e] += __shfl_down_sync(0xffffffffu, acc[e], o);
    if (lane == 0) {
        float m = acc[0];
        #pragma unroll
        for (int e = 1; e < E_; e++) m = fmaxf(m, acc[e]);
        float p[E_], sum = 0.f;
        #pragma unroll
        for (int e = 0; e < E_; e++) { p[e] = expf(acc[e] - m); sum += p[e]; }
        float inv = 1.f / sum;
        #pragma unroll
        for (int e = 0; e < E_; e++) { p[e] *= inv; out_probs[(size_t)tok * E_ + e] = p[e]; }
        int i0 = 0;
        #pragma unroll
        for (int e = 1; e < E_; e++) if (p[e] > p[i0]) i0 = e;
        int i1 = -1;
        #pragma unroll
        for (int e = 0; e < E_; e++) {
            if (e == i0) continue;
            if (i1 < 0 || p[e] > p[i1]) i1 = e;
        }
        int pos0 = atomicAdd(&g_cnt[i0], 1);
        g_tok[i0 * BV + pos0] = tok; g_w[i0 * BV + pos0] = p[i0]; g_slot[i0 * BV + pos0] = 0;
        int pos1 = atomicAdd(&g_cnt[i1], 1);
        g_tok[i1 * BV + pos1] = tok; g_w[i1 * BV + pos1] = p[i1]; g_slot[i1 * BV + pos1] = 1;
    }
}

// combine slots + relu + transpose back + residual -> g_x1 fp32 + g_x1_h fp16
__global__ void addres_kernel(const float* __restrict__ x) {
    __shared__ float tile[32][33];
    int b = blockIdx.z;
    int v0 = blockIdx.x * 32, s0 = blockIdx.y * 32;
    int tx = threadIdx.x, ty = threadIdx.y;
    #pragma unroll
    for (int r = 0; r < 32; r += 8) {
        size_t o = ((size_t)b * V_ + v0 + ty + r) * S_ + s0 + tx;
        tile[ty + r][tx] = g_part[0][o] + g_part[1][o];
    }
    __syncthreads();
    const float* xp = x + (size_t)b * S_ * V_;
    #pragma unroll
    for (int r = 0; r < 32; r += 8) {
        float tv = fmaxf(tile[tx][ty + r], 0.f);
        int s = s0 + ty + r, v = v0 + tx;
        size_t o = (size_t)s * V_ + v;
        float val = tv + xp[o];
        size_t bs = (size_t)b * S_ + s;
        g_x1[bs * V_ + v] = val;
        g_x1_h[bs * V_ + v] = __float2half(val);
    }
}

// ================= HMMA fp16 GEMM: 128x128 CTA tile, BK=32, double-buffered =================
// MODE 0: MoE (gathered A rows, scaled scatter to g_part)
// MODE 1: fc1 (bias+relu -> g_h_h fp16)
// MODE 2: fc2 (bias+residual -> out fp32)
#define LDA 40   // padded fp16 stride (conflict-free ldmatrix)

template<int MODE, int KDIM, int NDIM>
__global__ void __launch_bounds__(256) mma_kernel(const __half* __restrict__ A,
                                                  const __half* __restrict__ Bm,
                                                  const float* __restrict__ bias,
                                                  float* __restrict__ out) {
    constexpr int NKT = KDIM / 32;
    __shared__ __align__(16) __half sA[2][128 * LDA];
    __shared__ __align__(16) __half sB[2][128 * LDA];
    __shared__ int   s_tok[128];
    __shared__ float s_w[128];
    __shared__ int   s_slot[128];

    const int tid = threadIdx.x;
    const int e = (MODE == 0) ? blockIdx.z : 0;
    const int m0 = blockIdx.y * 128;
    const int n0 = blockIdx.x * 128;
    int cnt;
    if (MODE == 0) { cnt = g_cnt[e]; if (m0 >= cnt) return; }
    else cnt = 1 << 30;

    const __half* Bp = (MODE == 0) ? (Bm + (size_t)e * S_ * KDIM) : Bm;
    const float* biasp = (MODE == 0) ? (bias + e * S_) : bias;

    if (MODE == 0) {
        if (tid < 128) {
            int gr = m0 + tid;
            if (gr < cnt) { s_tok[tid] = g_tok[e * BV + gr]; s_w[tid] = g_w[e * BV + gr];
                            s_slot[tid] = g_slot[e * BV + gr]; }
            else          { s_tok[tid] = 0; s_w[tid] = 0.f; s_slot[tid] = 0; }
        }
        __syncthreads();
    }

    // per-thread gmem chunk map: 2 chunks for A, 2 for B (16B each)
    const __half* aptr[2];
    const __half* bptr[2];
    uint32_t sAo[2], sBo[2];
    #pragma unroll
    for (int i = 0; i < 2; i++) {
        int c = tid + i * 256;
        int row = c >> 2, kc = c & 3;
        if (MODE == 0) aptr[i] = A + (size_t)s_tok[row] * KDIM + kc * 8;
        else           aptr[i] = A + (size_t)(m0 + row) * KDIM + kc * 8;
        bptr[i] = Bp + (size_t)(n0 + row) * KDIM + kc * 8;
        sAo[i] = (uint32_t)(row * LDA + kc * 8);
        sBo[i] = sAo[i];
    }

    float acc[2][8][4];
    #pragma unroll
    for (int mi = 0; mi < 2; mi++)
        #pragma unroll
        for (int nf = 0; nf < 8; nf++)
            #pragma unroll
            for (int q = 0; q < 4; q++) acc[mi][nf][q] = 0.f;

    const int lane = tid & 31, wid = tid >> 5;
    const int wm = wid & 3, wn = wid >> 2;   // warp tile: rows wm*32, cols wn*64

    uint4 pa[2], pb[2];
    #pragma unroll
    for (int i = 0; i < 2; i++) {
        pa[i] = *reinterpret_cast<const uint4*>(aptr[i]);
        pb[i] = *reinterpret_cast<const uint4*>(bptr[i]);
    }
    #pragma unroll
    for (int i = 0; i < 2; i++) {
        *reinterpret_cast<uint4*>(&sA[0][sAo[i]]) = pa[i];
        *reinterpret_cast<uint4*>(&sB[0][sBo[i]]) = pb[i];
    }
    __syncthreads();

    const int a_r = wm * 32 + (lane & 15);
    const int b_r = wn * 64 + (lane & 7) + ((lane >> 3) & 1) * 8;
    const int k_half = (lane >> 4) << 3;

    #pragma unroll 1
    for (int kt = 0; kt < NKT; kt++) {
        const int cur = kt & 1;
        if (kt + 1 < NKT) {
            #pragma unroll
            for (int i = 0; i < 2; i++) {
                pa[i] = *reinterpret_cast<const uint4*>(aptr[i] + (kt + 1) * 32);
                pb[i] = *reinterpret_cast<const uint4*>(bptr[i] + (kt + 1) * 32);
            }
        }
        const uint32_t sAb = smem_u32(&sA[cur][0]);
        const uint32_t sBb = smem_u32(&sB[cur][0]);
        #pragma unroll
        for (int k16 = 0; k16 < 32; k16 += 16) {
            uint32_t aF[2][4], bF[4][4];
            #pragma unroll
            for (int mi = 0; mi < 2; mi++) {
                uint32_t ad = sAb + ((a_r + mi * 16) * LDA + k16 + k_half) * 2;
                LDSM4(aF[mi], ad);
            }
            #pragma unroll
            for (int nq = 0; nq < 4; nq++) {
                uint32_t bd = sBb + ((b_r + nq * 16) * LDA + k16 + k_half) * 2;
                LDSM4(bF[nq], bd);
            }
            #pragma unroll
            for (int mi = 0; mi < 2; mi++)
                #pragma unroll
                for (int nq = 0; nq < 4; nq++) {
                    MMA16816(acc[mi][nq * 2 + 0], aF[mi], bF[nq][0], bF[nq][2]);
                    MMA16816(acc[mi][nq * 2 + 1], aF[mi], bF[nq][1], bF[nq][3]);
                }
        }
        if (kt + 1 < NKT) {
            const int nxt = cur ^ 1;
            __syncthreads();   // all warps done reading buf nxt (iter kt-1)
            #pragma unroll
            for (int i = 0; i < 2; i++) {
                *reinterpret_cast<uint4*>(&sA[nxt][sAo[i]]) = pa[i];
                *reinterpret_cast<uint4*>(&sB[nxt][sBo[i]]) = pb[i];
            }
            __syncthreads();
        }
    }

    // ---- epilogue straight from C fragments ----
    const int g = lane >> 2, t = lane & 3;
    #pragma unroll
    for (int mi = 0; mi < 2; mi++) {
        #pragma unroll
        for (int nf = 0; nf < 8; nf++) {
            const int col = n0 + wn * 64 + nf * 8 + 2 * t;
            const float b0 = biasp[col], b1 = biasp[col + 1];
            #pragma unroll
            for (int h = 0; h < 2; h++) {   // h=0: row g, h=1: row g+8
                const int lr = wm * 32 + mi * 16 + g + h * 8;
                float v0 = acc[mi][nf][h * 2 + 0] + b0;
                float v1 = acc[mi][nf][h * 2 + 1] + b1;
                if (MODE == 0) {
                    if (m0 + lr < cnt) {
                        float wgt = s_w[lr];
                        float* dst = g_part[s_slot[lr]] + (size_t)s_tok[lr] * S_ + col;
                        *reinterpret_cast<float2*>(dst) = make_float2(wgt * v0, wgt * v1);
                    }
                } else if (MODE == 1) {
                    v0 = fmaxf(v0, 0.f); v1 = fmaxf(v1, 0.f);
                    size_t row = (size_t)(m0 + lr);
                    *reinterpret_cast<__half2*>(g_h_h + row * FF_ + col) =
                        __floats2half2_rn(v0, v1);
                } else {
                    size_t row = (size_t)(m0 + lr);
                    const float2 r2 = *reinterpret_cast<const float2*>(
                        g_x1 + row * NDIM + col);
                    *reinterpret_cast<float2*>(out + row * NDIM + col) =
                        make_float2(v0 + r2.x, v1 + r2.y);
                }
            }
        }
    }
}

// ================= launch =================
extern "C" void kernel_launch(void* const* d_in, const int* in_sizes, int n_in,
                              void* d_out, int out_size) {
    const float* x      = (const float*)d_in[0];
    const float* gate_W = (const float*)d_in[1];
    const float* exp_W  = (const float*)d_in[2];
    const float* exp_b  = (const float*)d_in[3];
    const float* fc1_W  = (const float*)d_in[4];
    const float* fc1_b  = (const float*)d_in[5];
    const float* fc2_W  = (const float*)d_in[6];
    const float* fc2_b  = (const float*)d_in[7];
    float* out       = (float*)d_out;
    float* out_probs = out + (size_t)B_ * S_ * V_;   // tuple: (x, probs)

    __half *p_xt_h, *p_eW, *p_f1W, *p_f2W, *p_x1_h, *p_h_h;
    cudaGetSymbolAddress((void**)&p_xt_h, g_xt_h);
    cudaGetSymbolAddress((void**)&p_eW,  g_eW_h);
    cudaGetSymbolAddress((void**)&p_f1W, g_f1W_h);
    cudaGetSymbolAddress((void**)&p_f2W, g_f2W_h);
    cudaGetSymbolAddress((void**)&p_x1_h, g_x1_h);
    cudaGetSymbolAddress((void**)&p_h_h,  g_h_h);

    dim3 tb(32, 8);
    zero_cnt_kernel<<<1, 32>>>();
    transpose_kernel<<<dim3(S_ / 32, V_ / 32, B_), tb>>>(x);
    cast_kernel<<<2048, 256>>>(exp_W, p_eW, (size_t)E_ * S_ * S_ / 4);
    cast_kernel<<<512, 256>>>(fc1_W, p_f1W, (size_t)FF_ * V_ / 4);
    cast_kernel<<<512, 256>>>(fc2_W, p_f2W, (size_t)V_ * FF_ / 4);
    gating_kernel<<<BV / 8, 256>>>(gate_W, out_probs);
    mma_kernel<0, S_, S_><<<dim3(S_ / 128, BV / 128, E_), 256>>>(
        p_xt_h, p_eW, exp_b, nullptr);
    addres_kernel<<<dim3(V_ / 32, S_ / 32, B_), tb>>>(x);
    mma_kernel<1, V_, FF_><<<dim3(FF_ / 128, BS / 128, 1), 256>>>(
        p_x1_h, p_f1W, fc1_b, nullptr);
    mma_kernel<2, FF_, V_><<<dim3(V_ / 128, BS / 128, 1), 256>>>(
        p_h_h, p_f2W, fc2_b, out);
}

// round 11
// speedup vs baseline: 5.4925x; 1.0785x over previous
#include <cuda_runtime.h>
#include <cuda_fp16.h>
#include <cstdint>
#include <math.h>

#define B_  16
#define S_  1024
#define V_  512
#define E_  8
#define FF_ 2048
#define BV  (B_*V_)   // 8192 tokens (b,v)
#define BS  (B_*S_)   // 16384 rows (b,s)

// ================= device scratch (no allocation allowed) =================
__device__ __align__(16) float  g_xt   [(size_t)BV * S_];      // x^T fp32 (gating)
__device__ __align__(16) __half g_xt_h [(size_t)BV * S_];      // MoE A (fp16)
__device__ __align__(16) float  g_part [2][(size_t)BV * S_];   // per-slot MoE outputs
__device__ __align__(16) float  g_x1   [(size_t)BS * V_];      // MoE+res fp32
__device__ __align__(16) __half g_x1_h [(size_t)BS * V_];      // fc1 A (fp16)
__device__ __align__(16) __half g_h_h  [(size_t)BS * FF_];     // fc2 A (fp16)
__device__ __align__(16) __half g_eW_h [(size_t)E_ * S_ * S_]; // MoE B (fp16)
__device__ __align__(16) __half g_f1W_h[(size_t)FF_ * V_];     // fc1 B
__device__ __align__(16) __half g_f2W_h[(size_t)V_ * FF_];     // fc2 B
__device__ int   g_tok [E_ * BV];
__device__ float g_w   [E_ * BV];
__device__ int   g_slot[E_ * BV];
__device__ int   g_cnt [E_];

__device__ __forceinline__ uint32_t smem_u32(const void* p) {
    uint32_t a;
    asm("{ .reg .u64 t; cvta.to.shared.u64 t, %1; cvt.u32.u64 %0, t; }" : "=r"(a) : "l"(p));
    return a;
}
#define LDSM4(r, a) \
    asm volatile("ldmatrix.sync.aligned.m8n8.x4.shared.b16 {%0,%1,%2,%3}, [%4];" \
                 : "=r"((r)[0]), "=r"((r)[1]), "=r"((r)[2]), "=r"((r)[3]) : "r"(a))
#define MMA16816(d, a, b0v, b1v) \
    asm volatile("mma.sync.aligned.m16n8k16.row.col.f32.f16.f16.f32 " \
                 "{%0,%1,%2,%3},{%4,%5,%6,%7},{%8,%9},{%0,%1,%2,%3};" \
                 : "+f"((d)[0]), "+f"((d)[1]), "+f"((d)[2]), "+f"((d)[3]) \
                 : "r"((a)[0]), "r"((a)[1]), "r"((a)[2]), "r"((a)[3]), "r"(b0v), "r"(b1v))
#define CP16(dst, src) \
    asm volatile("cp.async.cg.shared.global [%0], [%1], 16;" :: "r"(dst), "l"(src))
#define CP_COMMIT() asm volatile("cp.async.commit_group;" ::: "memory")
#define CP_WAIT1()  asm volatile("cp.async.wait_group 1;" ::: "memory")

// ================= small kernels =================
__global__ void zero_cnt_kernel() { if (threadIdx.x < E_) g_cnt[threadIdx.x] = 0; }

// fp32 -> fp16 cast (weights), vectorized 4-wide
__global__ void cast_kernel(const float* __restrict__ in, __half* __restrict__ out,
                            size_t total4) {
    size_t i = (size_t)blockIdx.x * blockDim.x + threadIdx.x;
    size_t stride = (size_t)gridDim.x * blockDim.x;
    for (size_t idx = i; idx < total4; idx += stride) {
        float4 v = reinterpret_cast<const float4*>(in)[idx];
        reinterpret_cast<__half2*>(out)[idx * 2 + 0] = __floats2half2_rn(v.x, v.y);
        reinterpret_cast<__half2*>(out)[idx * 2 + 1] = __floats2half2_rn(v.z, v.w);
    }
}

// transpose x[B,S,V] -> g_xt fp32 + g_xt_h fp16
__global__ void transpose_kernel(const float* __restrict__ x) {
    __shared__ float tile[32][33];
    int b = blockIdx.z;
    int s0 = blockIdx.x * 32, v0 = blockIdx.y * 32;
    int tx = threadIdx.x, ty = threadIdx.y;   // (32, 8)
    const float* xp = x + (size_t)b * S_ * V_;
    #pragma unroll
    for (int r = 0; r < 32; r += 8)
        tile[ty + r][tx] = xp[(size_t)(s0 + ty + r) * V_ + v0 + tx];
    __syncthreads();
    #pragma unroll
    for (int r = 0; r < 32; r += 8) {
        float v = tile[tx][ty + r];
        size_t o = ((size_t)b * V_ + v0 + ty + r) * S_ + s0 + tx;
        g_xt[o] = v;
        g_xt_h[o] = __float2half(v);
    }
}

// gating: softmax probs + top-2 expert lists (with slot ids)
__global__ void __launch_bounds__(256) gating_kernel(const float* __restrict__ gate_W,
                                                     float* __restrict__ out_probs) {
    __shared__ float sgw[E_ * S_];
    int tid = threadIdx.x;
    for (int i = tid; i < E_ * S_; i += 256) sgw[i] = gate_W[i];
    __syncthreads();
    int warp = tid >> 5, lane = tid & 31;
    int tok = blockIdx.x * 8 + warp;
    const float* row = g_xt + (size_t)tok * S_;
    float acc[E_] = {};
    for (int s = lane; s < S_; s += 32) {
        float xv = row[s];
        #pragma unroll
        for (int e = 0; e < E_; e++) acc[e] = fmaf(xv, sgw[e * S_ + s], acc[e]);
    }
    #pragma unroll
    for (int e = 0; e < E_; e++)
        #pragma unroll
        for (int o = 16; o > 0; o >>= 1)
            acc[e] += __shfl_down_sync(0xffffffffu, acc[e], o);
    if (lane == 0) {
        float m = acc[0];
        #pragma unroll
        for (int e = 1; e < E_; e++) m = fmaxf(m, acc[e]);
        float p[E_], sum = 0.f;
        #pragma unroll
        for (int e = 0; e < E_; e++) { p[e] = expf(acc[e] - m); sum += p[e]; }
        float inv = 1.f / sum;
        #pragma unroll
        for (int e = 0; e < E_; e++) { p[e] *= inv; out_probs[(size_t)tok * E_ + e] = p[e]; }
        int i0 = 0;
        #pragma unroll
        for (int e = 1; e < E_; e++) if (p[e] > p[i0]) i0 = e;
        int i1 = -1;
        #pragma unroll
        for (int e = 0; e < E_; e++) {
            if (e == i0) continue;
            if (i1 < 0 || p[e] > p[i1]) i1 = e;
        }
        int pos0 = atomicAdd(&g_cnt[i0], 1);
        g_tok[i0 * BV + pos0] = tok; g_w[i0 * BV + pos0] = p[i0]; g_slot[i0 * BV + pos0] = 0;
        int pos1 = atomicAdd(&g_cnt[i1], 1);
        g_tok[i1 * BV + pos1] = tok; g_w[i1 * BV + pos1] = p[i1]; g_slot[i1 * BV + pos1] = 1;
    }
}

// combine slots + relu + transpose back + residual -> g_x1 fp32 + g_x1_h fp16
__global__ void addres_kernel(const float* __restrict__ x) {
    __shared__ float tile[32][33];
    int b = blockIdx.z;
    int v0 = blockIdx.x * 32, s0 = blockIdx.y * 32;
    int tx = threadIdx.x, ty = threadIdx.y;
    #pragma unroll
    for (int r = 0; r < 32; r += 8) {
        size_t o = ((size_t)b * V_ + v0 + ty + r) * S_ + s0 + tx;
        tile[ty + r][tx] = g_part[0][o] + g_part[1][o];
    }
    __syncthreads();
    const float* xp = x + (size_t)b * S_ * V_;
    #pragma unroll
    for (int r = 0; r < 32; r += 8) {
        float tv = fmaxf(tile[tx][ty + r], 0.f);
        int s = s0 + ty + r, v = v0 + tx;
        size_t o = (size_t)s * V_ + v;
        float val = tv + xp[o];
        size_t bs = (size_t)b * S_ + s;
        g_x1[bs * V_ + v] = val;
        g_x1_h[bs * V_ + v] = __float2half(val);
    }
}

// ====== HMMA fp16 GEMM: 128x128 CTA tile, BK=32, 3-stage cp.async pipeline ======
// MODE 0: MoE (gathered A rows, scaled scatter to g_part)
// MODE 1: fc1 (bias+relu -> g_h_h fp16)
// MODE 2: fc2 (bias+residual -> out fp32)
#define LDA 40                 // padded fp16 stride (conflict-free ldmatrix)
#define AB_BYTES (128 * LDA * 2)          // 10240 per operand tile
#define STAGE_BYTES (2 * AB_BYTES)        // 20480 per stage (A + B)
#define NSTAGE 3
#define SMEM_DYN (NSTAGE * STAGE_BYTES)   // 61440

template<int MODE, int KDIM, int NDIM>
__global__ void __launch_bounds__(256, 2) mma_kernel(const __half* __restrict__ A,
                                                     const __half* __restrict__ Bm,
                                                     const float* __restrict__ bias,
                                                     float* __restrict__ out) {
    constexpr int NKT = KDIM / 32;
    extern __shared__ __align__(16) char smem[];
    __shared__ int   s_tok[128];
    __shared__ float s_w[128];
    __shared__ int   s_slot[128];

    const int tid = threadIdx.x;
    const int e = (MODE == 0) ? blockIdx.z : 0;
    const int m0 = blockIdx.y * 128;
    const int n0 = blockIdx.x * 128;
    int cnt;
    if (MODE == 0) { cnt = g_cnt[e]; if (m0 >= cnt) return; }
    else cnt = 1 << 30;

    const __half* Bp = (MODE == 0) ? (Bm + (size_t)e * S_ * KDIM) : Bm;
    const float* biasp = (MODE == 0) ? (bias + e * S_) : bias;

    if (MODE == 0) {
        if (tid < 128) {
            int gr = m0 + tid;
            if (gr < cnt) { s_tok[tid] = g_tok[e * BV + gr]; s_w[tid] = g_w[e * BV + gr];
                            s_slot[tid] = g_slot[e * BV + gr]; }
            else          { s_tok[tid] = 0; s_w[tid] = 0.f; s_slot[tid] = 0; }
        }
        __syncthreads();
    }

    // per-thread gmem chunk map: 2 chunks A + 2 chunks B (16B each) per stage
    const __half* aptr[2];
    const __half* bptr[2];
    uint32_t abo[2];   // byte offset within an operand tile
    #pragma unroll
    for (int i = 0; i < 2; i++) {
        int c = tid + i * 256;
        int row = c >> 2, kc = c & 3;
        if (MODE == 0) aptr[i] = A + (size_t)s_tok[row] * KDIM + kc * 8;
        else           aptr[i] = A + (size_t)(m0 + row) * KDIM + kc * 8;
        bptr[i] = Bp + (size_t)(n0 + row) * KDIM + kc * 8;
        abo[i] = (uint32_t)(row * (LDA * 2) + kc * 16);   // 80B rows: 16B-aligned
    }

    const uint32_t sbase = smem_u32(smem);
    auto issue_stage = [&](int kt, int slot) {
        const uint32_t sa = sbase + slot * STAGE_BYTES;
        const uint32_t sb = sa + AB_BYTES;
        const int koff = kt * 32;
        #pragma unroll
        for (int i = 0; i < 2; i++) CP16(sa + abo[i], aptr[i] + koff);
        #pragma unroll
        for (int i = 0; i < 2; i++) CP16(sb + abo[i], bptr[i] + koff);
    };

    float acc[2][8][4];
    #pragma unroll
    for (int mi = 0; mi < 2; mi++)
        #pragma unroll
        for (int nf = 0; nf < 8; nf++)
            #pragma unroll
            for (int q = 0; q < 4; q++) acc[mi][nf][q] = 0.f;

    const int lane = tid & 31, wid = tid >> 5;
    const int wm = wid & 3, wn = wid >> 2;   // warp tile: rows wm*32, cols wn*64
    const int a_r = wm * 32 + (lane & 15);
    const int b_r = wn * 64 + (lane & 7) + ((lane >> 3) & 1) * 8;
    const int k_half = (lane >> 4) << 3;

    issue_stage(0, 0); CP_COMMIT();
    issue_stage(1, 1); CP_COMMIT();

    #pragma unroll 1
    for (int kt = 0; kt < NKT; kt++) {
        CP_WAIT1();            // all but most-recent group complete => stage kt landed
        __syncthreads();       // all warps: stage kt visible, stage kt-1 reads done
        if (kt + 2 < NKT) issue_stage(kt + 2, (kt + 2) % NSTAGE);
        CP_COMMIT();

        const int slot = kt % NSTAGE;
        const uint32_t sAb = sbase + slot * STAGE_BYTES;
        const uint32_t sBb = sAb + AB_BYTES;
        #pragma unroll
        for (int k16 = 0; k16 < 32; k16 += 16) {
            uint32_t aF[2][4], bF[4][4];
            #pragma unroll
            for (int mi = 0; mi < 2; mi++) {
                uint32_t ad = sAb + ((a_r + mi * 16) * LDA + k16 + k_half) * 2;
                LDSM4(aF[mi], ad);
            }
            #pragma unroll
            for (int nq = 0; nq < 4; nq++) {
                uint32_t bd = sBb + ((b_r + nq * 16) * LDA + k16 + k_half) * 2;
                LDSM4(bF[nq], bd);
            }
            #pragma unroll
            for (int mi = 0; mi < 2; mi++)
                #pragma unroll
                for (int nq = 0; nq < 4; nq++) {
                    MMA16816(acc[mi][nq * 2 + 0], aF[mi], bF[nq][0], bF[nq][2]);
                    MMA16816(acc[mi][nq * 2 + 1], aF[mi], bF[nq][1], bF[nq][3]);
                }
        }
    }

    // ---- epilogue straight from C fragments ----
    const int g = lane >> 2, t = lane & 3;
    #pragma unroll
    for (int mi = 0; mi < 2; mi++) {
        #pragma unroll
        for (int nf = 0; nf < 8; nf++) {
            const int col = n0 + wn * 64 + nf * 8 + 2 * t;
            const float b0 = biasp[col], b1 = biasp[col + 1];
            #pragma unroll
            for (int h = 0; h < 2; h++) {   // h=0: row g, h=1: row g+8
                const int lr = wm * 32 + mi * 16 + g + h * 8;
                float v0 = acc[mi][nf][h * 2 + 0] + b0;
                float v1 = acc[mi][nf][h * 2 + 1] + b1;
                if (MODE == 0) {
                    if (m0 + lr < cnt) {
                        float wgt = s_w[lr];
                        float* dst = g_part[s_slot[lr]] + (size_t)s_tok[lr] * S_ + col;
                        *reinterpret_cast<float2*>(dst) = make_float2(wgt * v0, wgt * v1);
                    }
                } else if (MODE == 1) {
                    v0 = fmaxf(v0, 0.f); v1 = fmaxf(v1, 0.f);
                    size_t row = (size_t)(m0 + lr);
                    *reinterpret_cast<__half2*>(g_h_h + row * FF_ + col) =
                        __floats2half2_rn(v0, v1);
                } else {
                    size_t row = (size_t)(m0 + lr);
                    const float2 r2 = *reinterpret_cast<const float2*>(
                        g_x1 + row * NDIM + col);
                    *reinterpret_cast<float2*>(out + row * NDIM + col) =
                        make_float2(v0 + r2.x, v1 + r2.y);
                }
            }
        }
    }
}

// ================= launch =================
extern "C" void kernel_launch(void* const* d_in, const int* in_sizes, int n_in,
                              void* d_out, int out_size) {
    const float* x      = (const float*)d_in[0];
    const float* gate_W = (const float*)d_in[1];
    const float* exp_W  = (const float*)d_in[2];
    const float* exp_b  = (const float*)d_in[3];
    const float* fc1_W  = (const float*)d_in[4];
    const float* fc1_b  = (const float*)d_in[5];
    const float* fc2_W  = (const float*)d_in[6];
    const float* fc2_b  = (const float*)d_in[7];
    float* out       = (float*)d_out;
    float* out_probs = out + (size_t)B_ * S_ * V_;   // tuple: (x, probs)

    __half *p_xt_h, *p_eW, *p_f1W, *p_f2W, *p_x1_h, *p_h_h;
    cudaGetSymbolAddress((void**)&p_xt_h, g_xt_h);
    cudaGetSymbolAddress((void**)&p_eW,  g_eW_h);
    cudaGetSymbolAddress((void**)&p_f1W, g_f1W_h);
    cudaGetSymbolAddress((void**)&p_f2W, g_f2W_h);
    cudaGetSymbolAddress((void**)&p_x1_h, g_x1_h);
    cudaGetSymbolAddress((void**)&p_h_h,  g_h_h);

    cudaFuncSetAttribute(mma_kernel<0, S_, S_>,
                         cudaFuncAttributeMaxDynamicSharedMemorySize, SMEM_DYN);
    cudaFuncSetAttribute(mma_kernel<1, V_, FF_>,
                         cudaFuncAttributeMaxDynamicSharedMemorySize, SMEM_DYN);
    cudaFuncSetAttribute(mma_kernel<2, FF_, V_>,
                         cudaFuncAttributeMaxDynamicSharedMemorySize, SMEM_DYN);

    dim3 tb(32, 8);
    zero_cnt_kernel<<<1, 32>>>();
    transpose_kernel<<<dim3(S_ / 32, V_ / 32, B_), tb>>>(x);
    cast_kernel<<<2048, 256>>>(exp_W, p_eW, (size_t)E_ * S_ * S_ / 4);
    cast_kernel<<<512, 256>>>(fc1_W, p_f1W, (size_t)FF_ * V_ / 4);
    cast_kernel<<<512, 256>>>(fc2_W, p_f2W, (size_t)V_ * FF_ / 4);
    gating_kernel<<<BV / 8, 256>>>(gate_W, out_probs);
    mma_kernel<0, S_, S_><<<dim3(S_ / 128, BV / 128, E_), 256, SMEM_DYN>>>(
        p_xt_h, p_eW, exp_b, nullptr);
    addres_kernel<<<dim3(V_ / 32, S_ / 32, B_), tb>>>(x);
    mma_kernel<1, V_, FF_><<<dim3(FF_ / 128, BS / 128, 1), 256, SMEM_DYN>>>(
        p_x1_h, p_f1W, fc1_b, nullptr);
    mma_kernel<2, FF_, V_><<<dim3(V_ / 128, BS / 128, 1), 256, SMEM_DYN>>>(
        p_h_h, p_f2W, fc2_b, out);
}

// round 12
// speedup vs baseline: 5.5649x; 1.0132x over previous
#include <cuda_runtime.h>
#include <cuda_fp16.h>
#include <cstdint>
#include <math.h>

#define B_  16
#define S_  1024
#define V_  512
#define E_  8
#define FF_ 2048
#define BV  (B_*V_)   // 8192 tokens (b,v)
#define BS  (B_*S_)   // 16384 rows (b,s)

// ================= device scratch (no allocation allowed) =================
__device__ __align__(16) __half g_xt_h [(size_t)BV * S_];      // MoE A (fp16) = x^T
__device__ __align__(16) float  g_part [2][(size_t)BV * S_];   // per-slot MoE outputs
__device__ __align__(16) float  g_x1   [(size_t)BS * V_];      // MoE+res fp32
__device__ __align__(16) __half g_x1_h [(size_t)BS * V_];      // fc1 A (fp16)
__device__ __align__(16) __half g_h_h  [(size_t)BS * FF_];     // fc2 A (fp16)
__device__ __align__(16) __half g_eW_h [(size_t)E_ * S_ * S_]; // MoE B (fp16)
__device__ __align__(16) __half g_f1W_h[(size_t)FF_ * V_];     // fc1 B
__device__ __align__(16) __half g_f2W_h[(size_t)V_ * FF_];     // fc2 B
__device__ int   g_tok [E_ * BV];
__device__ float g_w   [E_ * BV];
__device__ int   g_slot[E_ * BV];
__device__ int   g_cnt [E_];

__device__ __forceinline__ uint32_t smem_u32(const void* p) {
    uint32_t a;
    asm("{ .reg .u64 t; cvta.to.shared.u64 t, %1; cvt.u32.u64 %0, t; }" : "=r"(a) : "l"(p));
    return a;
}
#define LDSM4(r, a) \
    asm volatile("ldmatrix.sync.aligned.m8n8.x4.shared.b16 {%0,%1,%2,%3}, [%4];" \
                 : "=r"((r)[0]), "=r"((r)[1]), "=r"((r)[2]), "=r"((r)[3]) : "r"(a))
#define MMA16816(d, a, b0v, b1v) \
    asm volatile("mma.sync.aligned.m16n8k16.row.col.f32.f16.f16.f32 " \
                 "{%0,%1,%2,%3},{%4,%5,%6,%7},{%8,%9},{%0,%1,%2,%3};" \
                 : "+f"((d)[0]), "+f"((d)[1]), "+f"((d)[2]), "+f"((d)[3]) \
                 : "r"((a)[0]), "r"((a)[1]), "r"((a)[2]), "r"((a)[3]), "r"(b0v), "r"(b1v))
#define CP16(dst, src) \
    asm volatile("cp.async.cg.shared.global [%0], [%1], 16;" :: "r"(dst), "l"(src))
#define CP_COMMIT() asm volatile("cp.async.commit_group;" ::: "memory")
#define CP_WAIT2()  asm volatile("cp.async.wait_group 2;" ::: "memory")

// ================= prep: zero counters + cast all 3 weight tensors =================
__global__ void prep_kernel(const float* __restrict__ eW, const float* __restrict__ f1W,
                            const float* __restrict__ f2W) {
    size_t i = (size_t)blockIdx.x * blockDim.x + threadIdx.x;
    size_t stride = (size_t)gridDim.x * blockDim.x;
    if (i < E_) g_cnt[i] = 0;
    const size_t n0 = (size_t)E_ * S_ * S_ / 4;     // eW float4 count
    const size_t n1 = (size_t)FF_ * V_ / 4;
    const size_t n2 = (size_t)V_ * FF_ / 4;
    for (size_t idx = i; idx < n0 + n1 + n2; idx += stride) {
        const float* src; __half* dst; size_t k;
        if (idx < n0)            { src = eW;  dst = g_eW_h;  k = idx; }
        else if (idx < n0 + n1)  { src = f1W; dst = g_f1W_h; k = idx - n0; }
        else                     { src = f2W; dst = g_f2W_h; k = idx - n0 - n1; }
        float4 v = reinterpret_cast<const float4*>(src)[k];
        reinterpret_cast<__half2*>(dst)[k * 2 + 0] = __floats2half2_rn(v.x, v.y);
        reinterpret_cast<__half2*>(dst)[k * 2 + 1] = __floats2half2_rn(v.z, v.w);
    }
}

// transpose x[B,S,V] -> g_xt_h fp16 only
__global__ void transpose_kernel(const float* __restrict__ x) {
    __shared__ float tile[32][33];
    int b = blockIdx.z;
    int s0 = blockIdx.x * 32, v0 = blockIdx.y * 32;
    int tx = threadIdx.x, ty = threadIdx.y;   // (32, 8)
    const float* xp = x + (size_t)b * S_ * V_;
    #pragma unroll
    for (int r = 0; r < 32; r += 8)
        tile[ty + r][tx] = xp[(size_t)(s0 + ty + r) * V_ + v0 + tx];
    __syncthreads();
    #pragma unroll
    for (int r = 0; r < 32; r += 8) {
        size_t o = ((size_t)b * V_ + v0 + ty + r) * S_ + s0 + tx;
        g_xt_h[o] = __float2half(tile[tx][ty + r]);
    }
}

// gating from x directly: block = (v-chunk of 32, batch b); fp32 math throughout
__global__ void __launch_bounds__(256) gating_kernel(const float* __restrict__ x,
                                                     const float* __restrict__ gate_W,
                                                     float* __restrict__ out_probs) {
    __shared__ float sgw[E_ * S_];         // 32 KB
    __shared__ float red[8][32][E_];       // 8 KB
    __shared__ float lsm[32][E_];
    const int tid = threadIdx.x;
    const int b = blockIdx.y, v0 = blockIdx.x * 32;
    for (int i = tid; i < E_ * S_; i += 256) sgw[i] = gate_W[i];
    __syncthreads();

    const int vl = tid & 31, sg = tid >> 5;   // warp sg handles rows s = sg, sg+8, ...
    float acc[E_] = {};
    const float* xp = x + (size_t)b * S_ * V_ + v0;
    for (int s = sg; s < S_; s += 8) {
        float xv = xp[(size_t)s * V_ + vl];   // 32 lanes: 128B coalesced
        #pragma unroll
        for (int e = 0; e < E_; e++) acc[e] = fmaf(xv, sgw[e * S_ + s], acc[e]);
    }
    #pragma unroll
    for (int e = 0; e < E_; e++) red[sg][vl][e] = acc[e];
    __syncthreads();
    if (tid < 256) {                       // (v,e) pair per thread
        int v = tid >> 3, e = tid & 7;
        float s = 0.f;
        #pragma unroll
        for (int g = 0; g < 8; g++) s += red[g][v][e];
        lsm[v][e] = s;
    }
    __syncthreads();
    if (tid < 32) {
        int tok = b * V_ + v0 + tid;
        float m = lsm[tid][0];
        #pragma unroll
        for (int e = 1; e < E_; e++) m = fmaxf(m, lsm[tid][e]);
        float p[E_], sum = 0.f;
        #pragma unroll
        for (int e = 0; e < E_; e++) { p[e] = expf(lsm[tid][e] - m); sum += p[e]; }
        float inv = 1.f / sum;
        #pragma unroll
        for (int e = 0; e < E_; e++) { p[e] *= inv; out_probs[(size_t)tok * E_ + e] = p[e]; }
        int i0 = 0;
        #pragma unroll
        for (int e = 1; e < E_; e++) if (p[e] > p[i0]) i0 = e;
        int i1 = -1;
        #pragma unroll
        for (int e = 0; e < E_; e++) {
            if (e == i0) continue;
            if (i1 < 0 || p[e] > p[i1]) i1 = e;
        }
        int pos0 = atomicAdd(&g_cnt[i0], 1);
        g_tok[i0 * BV + pos0] = tok; g_w[i0 * BV + pos0] = p[i0]; g_slot[i0 * BV + pos0] = 0;
        int pos1 = atomicAdd(&g_cnt[i1], 1);
        g_tok[i1 * BV + pos1] = tok; g_w[i1 * BV + pos1] = p[i1]; g_slot[i1 * BV + pos1] = 1;
    }
}

// combine slots + relu + transpose back + residual -> g_x1 fp32 + g_x1_h fp16
__global__ void addres_kernel(const float* __restrict__ x) {
    __shared__ float tile[32][33];
    int b = blockIdx.z;
    int v0 = blockIdx.x * 32, s0 = blockIdx.y * 32;
    int tx = threadIdx.x, ty = threadIdx.y;
    #pragma unroll
    for (int r = 0; r < 32; r += 8) {
        size_t o = ((size_t)b * V_ + v0 + ty + r) * S_ + s0 + tx;
        tile[ty + r][tx] = g_part[0][o] + g_part[1][o];
    }
    __syncthreads();
    const float* xp = x + (size_t)b * S_ * V_;
    #pragma unroll
    for (int r = 0; r < 32; r += 8) {
        float tv = fmaxf(tile[tx][ty + r], 0.f);
        int s = s0 + ty + r, v = v0 + tx;
        size_t o = (size_t)s * V_ + v;
        float val = tv + xp[o];
        size_t bs = (size_t)b * S_ + s;
        g_x1[bs * V_ + v] = val;
        g_x1_h[bs * V_ + v] = __float2half(val);
    }
}

// ====== HMMA fp16 GEMM: 128x128 CTA tile, BK=32, 4-stage cp.async pipeline ======
#define LDA 40                 // padded fp16 stride (conflict-free ldmatrix)
#define AB_BYTES (128 * LDA * 2)          // 10240 per operand tile
#define STAGE_BYTES (2 * AB_BYTES)        // 20480 per stage (A + B)
#define NSTAGE 4
#define SMEM_DYN (NSTAGE * STAGE_BYTES)   // 81920

template<int MODE, int KDIM, int NDIM>
__global__ void __launch_bounds__(256, 2) mma_kernel(const __half* __restrict__ A,
                                                     const __half* __restrict__ Bm,
                                                     const float* __restrict__ bias,
                                                     float* __restrict__ out) {
    constexpr int NKT = KDIM / 32;
    extern __shared__ __align__(16) char smem[];
    __shared__ int   s_tok[128];
    __shared__ float s_w[128];
    __shared__ int   s_slot[128];

    const int tid = threadIdx.x;
    const int e = (MODE == 0) ? blockIdx.z : 0;
    const int m0 = blockIdx.y * 128;
    const int n0 = blockIdx.x * 128;
    int cnt;
    if (MODE == 0) { cnt = g_cnt[e]; if (m0 >= cnt) return; }
    else cnt = 1 << 30;

    const __half* Bp = (MODE == 0) ? (Bm + (size_t)e * S_ * KDIM) : Bm;
    const float* biasp = (MODE == 0) ? (bias + e * S_) : bias;

    if (MODE == 0) {
        if (tid < 128) {
            int gr = m0 + tid;
            if (gr < cnt) { s_tok[tid] = g_tok[e * BV + gr]; s_w[tid] = g_w[e * BV + gr];
                            s_slot[tid] = g_slot[e * BV + gr]; }
            else          { s_tok[tid] = 0; s_w[tid] = 0.f; s_slot[tid] = 0; }
        }
        __syncthreads();
    }

    // per-thread gmem chunk map: 2 chunks A + 2 chunks B (16B each) per stage
    const __half* aptr[2];
    const __half* bptr[2];
    uint32_t abo[2];
    #pragma unroll
    for (int i = 0; i < 2; i++) {
        int c = tid + i * 256;
        int row = c >> 2, kc = c & 3;
        if (MODE == 0) aptr[i] = A + (size_t)s_tok[row] * KDIM + kc * 8;
        else           aptr[i] = A + (size_t)(m0 + row) * KDIM + kc * 8;
        bptr[i] = Bp + (size_t)(n0 + row) * KDIM + kc * 8;
        abo[i] = (uint32_t)(row * (LDA * 2) + kc * 16);   // 80B rows: 16B-aligned
    }

    const uint32_t sbase = smem_u32(smem);
    auto issue_stage = [&](int kt, int slot) {
        const uint32_t sa = sbase + slot * STAGE_BYTES;
        const uint32_t sb = sa + AB_BYTES;
        const int koff = kt * 32;
        #pragma unroll
        for (int i = 0; i < 2; i++) CP16(sa + abo[i], aptr[i] + koff);
        #pragma unroll
        for (int i = 0; i < 2; i++) CP16(sb + abo[i], bptr[i] + koff);
    };

    float acc[2][8][4];
    #pragma unroll
    for (int mi = 0; mi < 2; mi++)
        #pragma unroll
        for (int nf = 0; nf < 8; nf++)
            #pragma unroll
            for (int q = 0; q < 4; q++) acc[mi][nf][q] = 0.f;

    const int lane = tid & 31, wid = tid >> 5;
    const int wm = wid & 3, wn = wid >> 2;   // warp tile: rows wm*32, cols wn*64
    const int a_r = wm * 32 + (lane & 15);
    const int b_r = wn * 64 + (lane & 7) + ((lane >> 3) & 1) * 8;
    const int k_half = (lane >> 4) << 3;

    issue_stage(0, 0); CP_COMMIT();
    issue_stage(1, 1); CP_COMMIT();
    issue_stage(2, 2); CP_COMMIT();

    #pragma unroll 1
    for (int kt = 0; kt < NKT; kt++) {
        CP_WAIT2();            // all but 2 newest groups done => stage kt landed
        __syncthreads();       // stage kt visible to all; slot (kt+3)%4 reads drained
        if (kt + 3 < NKT) issue_stage(kt + 3, (kt + 3) % NSTAGE);
        CP_COMMIT();

        const int slot = kt % NSTAGE;
        const uint32_t sAb = sbase + slot * STAGE_BYTES;
        const uint32_t sBb = sAb + AB_BYTES;
        #pragma unroll
        for (int k16 = 0; k16 < 32; k16 += 16) {
            uint32_t aF[2][4], bF[4][4];
            #pragma unroll
            for (int mi = 0; mi < 2; mi++) {
                uint32_t ad = sAb + ((a_r + mi * 16) * LDA + k16 + k_half) * 2;
                LDSM4(aF[mi], ad);
            }
            #pragma unroll
            for (int nq = 0; nq < 4; nq++) {
                uint32_t bd = sBb + ((b_r + nq * 16) * LDA + k16 + k_half) * 2;
                LDSM4(bF[nq], bd);
            }
            #pragma unroll
            for (int mi = 0; mi < 2; mi++)
                #pragma unroll
                for (int nq = 0; nq < 4; nq++) {
                    MMA16816(acc[mi][nq * 2 + 0], aF[mi], bF[nq][0], bF[nq][2]);
                    MMA16816(acc[mi][nq * 2 + 1], aF[mi], bF[nq][1], bF[nq][3]);
                }
        }
    }

    // ---- epilogue straight from C fragments ----
    const int g = lane >> 2, t = lane & 3;
    #pragma unroll
    for (int mi = 0; mi < 2; mi++) {
        #pragma unroll
        for (int nf = 0; nf < 8; nf++) {
            const int col = n0 + wn * 64 + nf * 8 + 2 * t;
            const float b0 = biasp[col], b1 = biasp[col + 1];
            #pragma unroll
            for (int h = 0; h < 2; h++) {   // h=0: row g, h=1: row g+8
                const int lr = wm * 32 + mi * 16 + g + h * 8;
                float v0 = acc[mi][nf][h * 2 + 0] + b0;
                float v1 = acc[mi][nf][h * 2 + 1] + b1;
                if (MODE == 0) {
                    if (m0 + lr < cnt) {
                        float wgt = s_w[lr];
                        float* dst = g_part[s_slot[lr]] + (size_t)s_tok[lr] * S_ + col;
                        *reinterpret_cast<float2*>(dst) = make_float2(wgt * v0, wgt * v1);
                    }
                } else if (MODE == 1) {
                    v0 = fmaxf(v0, 0.f); v1 = fmaxf(v1, 0.f);
                    size_t row = (size_t)(m0 + lr);
                    *reinterpret_cast<__half2*>(g_h_h + row * FF_ + col) =
                        __floats2half2_rn(v0, v1);
                } else {
                    size_t row = (size_t)(m0 + lr);
                    const float2 r2 = *reinterpret_cast<const float2*>(
                        g_x1 + row * NDIM + col);
                    *reinterpret_cast<float2*>(out + row * NDIM + col) =
                        make_float2(v0 + r2.x, v1 + r2.y);
                }
            }
        }
    }
}

// ================= launch =================
extern "C" void kernel_launch(void* const* d_in, const int* in_sizes, int n_in,
                              void* d_out, int out_size) {
    const float* x      = (const float*)d_in[0];
    const float* gate_W = (const float*)d_in[1];
    const float* exp_W  = (const float*)d_in[2];
    const float* exp_b  = (const float*)d_in[3];
    const float* fc1_W  = (const float*)d_in[4];
    const float* fc1_b  = (const float*)d_in[5];
    const float* fc2_W  = (const float*)d_in[6];
    const float* fc2_b  = (const float*)d_in[7];
    float* out       = (float*)d_out;
    float* out_probs = out + (size_t)B_ * S_ * V_;   // tuple: (x, probs)

    __half *p_xt_h, *p_eW, *p_f1W, *p_f2W, *p_x1_h, *p_h_h;
    cudaGetSymbolAddress((void**)&p_xt_h, g_xt_h);
    cudaGetSymbolAddress((void**)&p_eW,  g_eW_h);
    cudaGetSymbolAddress((void**)&p_f1W, g_f1W_h);
    cudaGetSymbolAddress((void**)&p_f2W, g_f2W_h);
    cudaGetSymbolAddress((void**)&p_x1_h, g_x1_h);
    cudaGetSymbolAddress((void**)&p_h_h,  g_h_h);

    cudaFuncSetAttribute(mma_kernel<0, S_, S_>,
                         cudaFuncAttributeMaxDynamicSharedMemorySize, SMEM_DYN);
    cudaFuncSetAttribute(mma_kernel<1, V_, FF_>,
                         cudaFuncAttributeMaxDynamicSharedMemorySize, SMEM_DYN);
    cudaFuncSetAttribute(mma_kernel<2, FF_, V_>,
                         cudaFuncAttributeMaxDynamicSharedMemorySize, SMEM_DYN);

    dim3 tb(32, 8);
    prep_kernel<<<2048, 256>>>(exp_W, fc1_W, fc2_W);
    gating_kernel<<<dim3(V_ / 32, B_), 256>>>(x, gate_W, out_probs);
    transpose_kernel<<<dim3(S_ / 32, V_ / 32, B_), tb>>>(x);
    mma_kernel<0, S_, S_><<<dim3(S_ / 128, BV / 128, E_), 256, SMEM_DYN>>>(
        p_xt_h, p_eW, exp_b, nullptr);
    addres_kernel<<<dim3(V_ / 32, S_ / 32, B_), tb>>>(x);
    mma_kernel<1, V_, FF_><<<dim3(FF_ / 128, BS / 128, 1), 256, SMEM_DYN>>>(
        p_x1_h, p_f1W, fc1_b, nullptr);
    mma_kernel<2, FF_, V_><<<dim3(V_ / 128, BS / 128, 1), 256, SMEM_DYN>>>(
        p_h_h, p_f2W, fc2_b, out);
}

// round 13
// speedup vs baseline: 6.0256x; 1.0828x over previous
#include <cuda_runtime.h>
#include <cuda_fp16.h>
#include <cstdint>
#include <math.h>

#define B_  16
#define S_  1024
#define V_  512
#define E_  8
#define FF_ 2048
#define BV  (B_*V_)   // 8192 tokens (b,v)
#define BS  (B_*S_)   // 16384 rows (b,s)

// ================= device scratch (no allocation allowed) =================
__device__ __align__(16) __half g_xt_h [(size_t)BV * S_];      // MoE A (fp16) = x^T
__device__ __align__(16) float  g_part [2][(size_t)BV * S_];   // per-slot MoE outputs
__device__ __align__(16) float  g_x1   [(size_t)BS * V_];      // MoE+res fp32
__device__ __align__(16) __half g_x1_h [(size_t)BS * V_];      // fc1 A (fp16)
__device__ __align__(16) __half g_h_h  [(size_t)BS * FF_];     // fc2 A (fp16)
__device__ __align__(16) __half g_eW_h [(size_t)E_ * S_ * S_]; // MoE B (fp16)
__device__ __align__(16) __half g_f1W_h[(size_t)FF_ * V_];     // fc1 B
__device__ __align__(16) __half g_f2W_h[(size_t)V_ * FF_];     // fc2 B
__device__ int   g_tok [E_ * BV];
__device__ float g_w   [E_ * BV];
__device__ int   g_slot[E_ * BV];
__device__ int   g_cnt [E_];

__device__ __forceinline__ uint32_t smem_u32(const void* p) {
    uint32_t a;
    asm("{ .reg .u64 t; cvta.to.shared.u64 t, %1; cvt.u32.u64 %0, t; }" : "=r"(a) : "l"(p));
    return a;
}
#define LDSM4(r, a) \
    asm volatile("ldmatrix.sync.aligned.m8n8.x4.shared.b16 {%0,%1,%2,%3}, [%4];" \
                 : "=r"((r)[0]), "=r"((r)[1]), "=r"((r)[2]), "=r"((r)[3]) : "r"(a))
#define MMA16816(d, a, b0v, b1v) \
    asm volatile("mma.sync.aligned.m16n8k16.row.col.f32.f16.f16.f32 " \
                 "{%0,%1,%2,%3},{%4,%5,%6,%7},{%8,%9},{%0,%1,%2,%3};" \
                 : "+f"((d)[0]), "+f"((d)[1]), "+f"((d)[2]), "+f"((d)[3]) \
                 : "r"((a)[0]), "r"((a)[1]), "r"((a)[2]), "r"((a)[3]), "r"(b0v), "r"(b1v))
#define CP16(dst, src) \
    asm volatile("cp.async.cg.shared.global [%0], [%1], 16;" :: "r"(dst), "l"(src))
#define CP_COMMIT() asm volatile("cp.async.commit_group;" ::: "memory")
#define CP_WAIT0()  asm volatile("cp.async.wait_group 0;" ::: "memory")

// ================= prep: zero counters + cast all 3 weight tensors =================
__global__ void prep_kernel(const float* __restrict__ eW, const float* __restrict__ f1W,
                            const float* __restrict__ f2W) {
    size_t i = (size_t)blockIdx.x * blockDim.x + threadIdx.x;
    size_t stride = (size_t)gridDim.x * blockDim.x;
    if (i < E_) g_cnt[i] = 0;
    const size_t n0 = (size_t)E_ * S_ * S_ / 4;     // eW float4 count
    const size_t n1 = (size_t)FF_ * V_ / 4;
    const size_t n2 = (size_t)V_ * FF_ / 4;
    for (size_t idx = i; idx < n0 + n1 + n2; idx += stride) {
        const float* src; __half* dst; size_t k;
        if (idx < n0)            { src = eW;  dst = g_eW_h;  k = idx; }
        else if (idx < n0 + n1)  { src = f1W; dst = g_f1W_h; k = idx - n0; }
        else                     { src = f2W; dst = g_f2W_h; k = idx - n0 - n1; }
        float4 v = reinterpret_cast<const float4*>(src)[k];
        reinterpret_cast<__half2*>(dst)[k * 2 + 0] = __floats2half2_rn(v.x, v.y);
        reinterpret_cast<__half2*>(dst)[k * 2 + 1] = __floats2half2_rn(v.z, v.w);
    }
}

// transpose x[B,S,V] -> g_xt_h fp16 only
__global__ void transpose_kernel(const float* __restrict__ x) {
    __shared__ float tile[32][33];
    int b = blockIdx.z;
    int s0 = blockIdx.x * 32, v0 = blockIdx.y * 32;
    int tx = threadIdx.x, ty = threadIdx.y;   // (32, 8)
    const float* xp = x + (size_t)b * S_ * V_;
    #pragma unroll
    for (int r = 0; r < 32; r += 8)
        tile[ty + r][tx] = xp[(size_t)(s0 + ty + r) * V_ + v0 + tx];
    __syncthreads();
    #pragma unroll
    for (int r = 0; r < 32; r += 8) {
        size_t o = ((size_t)b * V_ + v0 + ty + r) * S_ + s0 + tx;
        g_xt_h[o] = __float2half(tile[tx][ty + r]);
    }
}

// gating from x directly: block = (v-chunk of 32, batch b); fp32 math throughout
__global__ void __launch_bounds__(256) gating_kernel(const float* __restrict__ x,
                                                     const float* __restrict__ gate_W,
                                                     float* __restrict__ out_probs) {
    __shared__ float sgw[E_ * S_];         // 32 KB
    __shared__ float red[8][32][E_];       // 8 KB
    __shared__ float lsm[32][E_];
    const int tid = threadIdx.x;
    const int b = blockIdx.y, v0 = blockIdx.x * 32;
    for (int i = tid; i < E_ * S_; i += 256) sgw[i] = gate_W[i];
    __syncthreads();

    const int vl = tid & 31, sg = tid >> 5;   // warp sg handles rows s = sg, sg+8, ...
    float acc[E_] = {};
    const float* xp = x + (size_t)b * S_ * V_ + v0;
    for (int s = sg; s < S_; s += 8) {
        float xv = xp[(size_t)s * V_ + vl];   // 32 lanes: 128B coalesced
        #pragma unroll
        for (int e = 0; e < E_; e++) acc[e] = fmaf(xv, sgw[e * S_ + s], acc[e]);
    }
    #pragma unroll
    for (int e = 0; e < E_; e++) red[sg][vl][e] = acc[e];
    __syncthreads();
    {                                      // (v,e) pair per thread
        int v = tid >> 3, e = tid & 7;
        float s = 0.f;
        #pragma unroll
        for (int g = 0; g < 8; g++) s += red[g][v][e];
        lsm[v][e] = s;
    }
    __syncthreads();
    if (tid < 32) {
        int tok = b * V_ + v0 + tid;
        float m = lsm[tid][0];
        #pragma unroll
        for (int e = 1; e < E_; e++) m = fmaxf(m, lsm[tid][e]);
        float p[E_], sum = 0.f;
        #pragma unroll
        for (int e = 0; e < E_; e++) { p[e] = expf(lsm[tid][e] - m); sum += p[e]; }
        float inv = 1.f / sum;
        #pragma unroll
        for (int e = 0; e < E_; e++) { p[e] *= inv; out_probs[(size_t)tok * E_ + e] = p[e]; }
        int i0 = 0;
        #pragma unroll
        for (int e = 1; e < E_; e++) if (p[e] > p[i0]) i0 = e;
        int i1 = -1;
        #pragma unroll
        for (int e = 0; e < E_; e++) {
            if (e == i0) continue;
            if (i1 < 0 || p[e] > p[i1]) i1 = e;
        }
        int pos0 = atomicAdd(&g_cnt[i0], 1);
        g_tok[i0 * BV + pos0] = tok; g_w[i0 * BV + pos0] = p[i0]; g_slot[i0 * BV + pos0] = 0;
        int pos1 = atomicAdd(&g_cnt[i1], 1);
        g_tok[i1 * BV + pos1] = tok; g_w[i1 * BV + pos1] = p[i1]; g_slot[i1 * BV + pos1] = 1;
    }
}

// combine slots + relu + transpose back + residual -> g_x1 fp32 + g_x1_h fp16
__global__ void addres_kernel(const float* __restrict__ x) {
    __shared__ float tile[32][33];
    int b = blockIdx.z;
    int v0 = blockIdx.x * 32, s0 = blockIdx.y * 32;
    int tx = threadIdx.x, ty = threadIdx.y;
    #pragma unroll
    for (int r = 0; r < 32; r += 8) {
        size_t o = ((size_t)b * V_ + v0 + ty + r) * S_ + s0 + tx;
        tile[ty + r][tx] = g_part[0][o] + g_part[1][o];
    }
    __syncthreads();
    const float* xp = x + (size_t)b * S_ * V_;
    #pragma unroll
    for (int r = 0; r < 32; r += 8) {
        float tv = fmaxf(tile[tx][ty + r], 0.f);
        int s = s0 + ty + r, v = v0 + tx;
        size_t o = (size_t)s * V_ + v;
        float val = tv + xp[o];
        size_t bs = (size_t)b * S_ + s;
        g_x1[bs * V_ + v] = val;
        g_x1_h[bs * V_ + v] = __float2half(val);
    }
}

// ====== HMMA fp16 GEMM: 128x128 CTA tile, BK=64, 2-stage cp.async pipeline ======
// MODE 0: MoE (gathered A rows, scaled scatter to g_part)
// MODE 1: fc1 (bias+relu -> g_h_h fp16)
// MODE 2: fc2 (bias+residual -> out fp32)
#define LDA 72                            // 144B row stride: ldmatrix conflict-free
#define AB_BYTES (128 * LDA * 2)          // 18432 per operand tile (128 x 64 halfs)
#define STAGE_BYTES (2 * AB_BYTES)        // 36864 per stage (A + B)
#define SMEM_DYN (2 * STAGE_BYTES)        // 73728

template<int MODE, int KDIM, int NDIM>
__global__ void __launch_bounds__(256, 2) mma_kernel(const __half* __restrict__ A,
                                                     const __half* __restrict__ Bm,
                                                     const float* __restrict__ bias,
                                                     float* __restrict__ out) {
    constexpr int NKT = KDIM / 64;
    extern __shared__ __align__(16) char smem[];
    __shared__ int   s_tok[128];
    __shared__ float s_w[128];
    __shared__ int   s_slot[128];

    const int tid = threadIdx.x;
    const int e = (MODE == 0) ? blockIdx.z : 0;
    const int m0 = blockIdx.y * 128;
    const int n0 = blockIdx.x * 128;
    int cnt;
    if (MODE == 0) { cnt = g_cnt[e]; if (m0 >= cnt) return; }
    else cnt = 1 << 30;

    const __half* Bp = (MODE == 0) ? (Bm + (size_t)e * S_ * KDIM) : Bm;
    const float* biasp = (MODE == 0) ? (bias + e * S_) : bias;

    if (MODE == 0) {
        if (tid < 128) {
            int gr = m0 + tid;
            if (gr < cnt) { s_tok[tid] = g_tok[e * BV + gr]; s_w[tid] = g_w[e * BV + gr];
                            s_slot[tid] = g_slot[e * BV + gr]; }
            else          { s_tok[tid] = 0; s_w[tid] = 0.f; s_slot[tid] = 0; }
        }
        __syncthreads();
    }

    // per-thread gmem chunk map: 4 chunks A + 4 chunks B (16B each) per stage.
    // tile = 128 rows x 64 halfs (128B = 8 chunks/row); 1024 chunks / 256 thr = 4.
    // chunk c: row = c >> 3, kc = c & 7
    const __half* aptr[4];
    const __half* bptr[4];
    uint32_t abo[4];
    #pragma unroll
    for (int i = 0; i < 4; i++) {
        int c = tid + i * 256;
        int row = c >> 3, kc = c & 7;
        if (MODE == 0) aptr[i] = A + (size_t)s_tok[row] * KDIM + kc * 8;
        else           aptr[i] = A + (size_t)(m0 + row) * KDIM + kc * 8;
        bptr[i] = Bp + (size_t)(n0 + row) * KDIM + kc * 8;
        abo[i] = (uint32_t)(row * (LDA * 2) + kc * 16);   // 144B rows: 16B-aligned
    }

    const uint32_t sbase = smem_u32(smem);
    auto issue_stage = [&](int kt, int slot) {
        const uint32_t sa = sbase + slot * STAGE_BYTES;
        const uint32_t sb = sa + AB_BYTES;
        const int koff = kt * 64;
        #pragma unroll
        for (int i = 0; i < 4; i++) CP16(sa + abo[i], aptr[i] + koff);
        #pragma unroll
        for (int i = 0; i < 4; i++) CP16(sb + abo[i], bptr[i] + koff);
    };

    float acc[2][8][4];
    #pragma unroll
    for (int mi = 0; mi < 2; mi++)
        #pragma unroll
        for (int nf = 0; nf < 8; nf++)
            #pragma unroll
            for (int q = 0; q < 4; q++) acc[mi][nf][q] = 0.f;

    const int lane = tid & 31, wid = tid >> 5;
    const int wm = wid & 3, wn = wid >> 2;   // warp tile: rows wm*32, cols wn*64
    const int a_r = wm * 32 + (lane & 15);
    const int b_r = wn * 64 + (lane & 7) + ((lane >> 3) & 1) * 8;
    const int k_half = (lane >> 4) << 3;

    issue_stage(0, 0); CP_COMMIT();

    #pragma unroll 1
    for (int kt = 0; kt < NKT; kt++) {
        CP_WAIT0();            // stage kt landed (only outstanding group)
        __syncthreads();       // visible to all; other slot's reads drained
        if (kt + 1 < NKT) { issue_stage(kt + 1, (kt + 1) & 1); CP_COMMIT(); }

        const uint32_t sAb = sbase + (kt & 1) * STAGE_BYTES;
        const uint32_t sBb = sAb + AB_BYTES;
        #pragma unroll
        for (int k16 = 0; k16 < 64; k16 += 16) {
            uint32_t aF[2][4], bF[4][4];
            #pragma unroll
            for (int mi = 0; mi < 2; mi++) {
                uint32_t ad = sAb + ((a_r + mi * 16) * LDA + k16 + k_half) * 2;
                LDSM4(aF[mi], ad);
            }
            #pragma unroll
            for (int nq = 0; nq < 4; nq++) {
                uint32_t bd = sBb + ((b_r + nq * 16) * LDA + k16 + k_half) * 2;
                LDSM4(bF[nq], bd);
            }
            #pragma unroll
            for (int mi = 0; mi < 2; mi++)
                #pragma unroll
                for (int nq = 0; nq < 4; nq++) {
                    MMA16816(acc[mi][nq * 2 + 0], aF[mi], bF[nq][0], bF[nq][2]);
                    MMA16816(acc[mi][nq * 2 + 1], aF[mi], bF[nq][1], bF[nq][3]);
                }
        }
    }

    // ---- epilogue straight from C fragments ----
    const int g = lane >> 2, t = lane & 3;
    #pragma unroll
    for (int mi = 0; mi < 2; mi++) {
        #pragma unroll
        for (int nf = 0; nf < 8; nf++) {
            const int col = n0 + wn * 64 + nf * 8 + 2 * t;
            const float b0 = biasp[col], b1 = biasp[col + 1];
            #pragma unroll
            for (int h = 0; h < 2; h++) {   // h=0: row g, h=1: row g+8
                const int lr = wm * 32 + mi * 16 + g + h * 8;
                float v0 = acc[mi][nf][h * 2 + 0] + b0;
                float v1 = acc[mi][nf][h * 2 + 1] + b1;
                if (MODE == 0) {
                    if (m0 + lr < cnt) {
                        float wgt = s_w[lr];
                        float* dst = g_part[s_slot[lr]] + (size_t)s_tok[lr] * S_ + col;
                        *reinterpret_cast<float2*>(dst) = make_float2(wgt * v0, wgt * v1);
                    }
                } else if (MODE == 1) {
                    v0 = fmaxf(v0, 0.f); v1 = fmaxf(v1, 0.f);
                    size_t row = (size_t)(m0 + lr);
                    *reinterpret_cast<__half2*>(g_h_h + row * FF_ + col) =
                        __floats2half2_rn(v0, v1);
                } else {
                    size_t row = (size_t)(m0 + lr);
                    const float2 r2 = *reinterpret_cast<const float2*>(
                        g_x1 + row * NDIM + col);
                    *reinterpret_cast<float2*>(out + row * NDIM + col) =
                        make_float2(v0 + r2.x, v1 + r2.y);
                }
            }
        }
    }
}

// ================= launch =================
extern "C" void kernel_launch(void* const* d_in, const int* in_sizes, int n_in,
                              void* d_out, int out_size) {
    const float* x      = (const float*)d_in[0];
    const float* gate_W = (const float*)d_in[1];
    const float* exp_W  = (const float*)d_in[2];
    const float* exp_b  = (const float*)d_in[3];
    const float* fc1_W  = (const float*)d_in[4];
    const float* fc1_b  = (const float*)d_in[5];
    const float* fc2_W  = (const float*)d_in[6];
    const float* fc2_b  = (const float*)d_in[7];
    float* out       = (float*)d_out;
    float* out_probs = out + (size_t)B_ * S_ * V_;   // tuple: (x, probs)

    __half *p_xt_h, *p_eW, *p_f1W, *p_f2W, *p_x1_h, *p_h_h;
    cudaGetSymbolAddress((void**)&p_xt_h, g_xt_h);
    cudaGetSymbolAddress((void**)&p_eW,  g_eW_h);
    cudaGetSymbolAddress((void**)&p_f1W, g_f1W_h);
    cudaGetSymbolAddress((void**)&p_f2W, g_f2W_h);
    cudaGetSymbolAddress((void**)&p_x1_h, g_x1_h);
    cudaGetSymbolAddress((void**)&p_h_h,  g_h_h);

    cudaFuncSetAttribute(mma_kernel<0, S_, S_>,
                         cudaFuncAttributeMaxDynamicSharedMemorySize, SMEM_DYN);
    cudaFuncSetAttribute(mma_kernel<1, V_, FF_>,
                         cudaFuncAttributeMaxDynamicSharedMemorySize, SMEM_DYN);
    cudaFuncSetAttribute(mma_kernel<2, FF_, V_>,
                         cudaFuncAttributeMaxDynamicSharedMemorySize, SMEM_DYN);

    dim3 tb(32, 8);
    prep_kernel<<<2048, 256>>>(exp_W, fc1_W, fc2_W);
    gating_kernel<<<dim3(V_ / 32, B_), 256>>>(x, gate_W, out_probs);
    transpose_kernel<<<dim3(S_ / 32, V_ / 32, B_), tb>>>(x);
    mma_kernel<0, S_, S_><<<dim3(S_ / 128, BV / 128, E_), 256, SMEM_DYN>>>(
        p_xt_h, p_eW, exp_b, nullptr);
    addres_kernel<<<dim3(V_ / 32, S_ / 32, B_), tb>>>(x);
    mma_kernel<1, V_, FF_><<<dim3(FF_ / 128, BS / 128, 1), 256, SMEM_DYN>>>(
        p_x1_h, p_f1W, fc1_b, nullptr);
    mma_kernel<2, FF_, V_><<<dim3(V_ / 128, BS / 128, 1), 256, SMEM_DYN>>>(
        p_h_h, p_f2W, fc2_b, out);
}